// round 4
// baseline (speedup 1.0000x reference)
#include <cuda_runtime.h>
#include <math.h>
#include <stdint.h>

#define TTOK 4096
#define HDIM 2048
#define IDIM 1408
#define NEXP 8
#define FINAL_ELEMS (TTOK*HDIM)
#define MAXROWS (TTOK*2)

#define BM 128
#define BN 64
#define BK 32
#define KP 36   // legacy-path smem row stride

#define GU_SMEM 67584
#define DN_SMEM 51200

// ---------------- scratch ----------------
__device__ int   g_cnt[NEXP];
__device__ int   g_off[NEXP];
__device__ int   g_cur[NEXP];
__device__ int   g_tok[MAXROWS];
__device__ float g_wt [MAXROWS];
__device__ int   g_tidx[TTOK*2];
__device__ float g_tw  [TTOK*2];
__device__ float g_act[(size_t)MAXROWS*IDIM];

// ---------------- common helpers ----------------
__device__ __forceinline__ uint32_t smem_u32(const void* p){
    uint32_t a;
    asm("{ .reg .u64 t; cvta.to.shared.u64 t, %1; cvt.u32.u64 %0, t; }" : "=r"(a) : "l"(p));
    return a;
}
__device__ __forceinline__ float tf32r(float f){
    unsigned u; asm("cvt.rna.tf32.f32 %0, %1;" : "=r"(u) : "f"(f));
    return __uint_as_float(u);
}
__device__ __forceinline__ void mma8(float* c, const uint32_t* a, uint32_t b0, uint32_t b1){
    asm volatile(
      "mma.sync.aligned.m16n8k8.row.col.f32.tf32.tf32.f32 "
      "{%0,%1,%2,%3},{%4,%5,%6,%7},{%8,%9},{%0,%1,%2,%3};\n"
      : "+f"(c[0]),"+f"(c[1]),"+f"(c[2]),"+f"(c[3])
      : "r"(a[0]),"r"(a[1]),"r"(a[2]),"r"(a[3]),"r"(b0),"r"(b1));
}
__device__ __forceinline__ void ldsm4(uint32_t* d, uint32_t addr){
    asm volatile("ldmatrix.sync.aligned.m8n8.x4.shared.b16 {%0,%1,%2,%3}, [%4];"
      : "=r"(d[0]),"=r"(d[1]),"=r"(d[2]),"=r"(d[3]) : "r"(addr));
}

#if defined(__CUDA_ARCH_FEAT_SM103_ALL) || defined(__CUDA_ARCH_FEAT_SM100_ALL)
#define HAS_TC 1
__device__ __forceinline__ uint32_t sw128(uint32_t off){ return off ^ ((off >> 3) & 0x70u); }
static __device__ __forceinline__ uint64_t make_desc(uint32_t smem_addr){
    const uint64_t base = (uint64_t(2) << 61) | (uint64_t(1) << 46) |
                          (uint64_t(64) << 32) | (uint64_t(1) << 16);
    return base | ((uint64_t)(smem_addr >> 4) & 0x3FFFu);
}
#define IDESC_TF32 ((1u<<4) | (2u<<7) | (2u<<10) | ((BN/8u)<<17) | ((BM/16u)<<24))
__device__ __forceinline__ void mma_tf32(uint32_t d, uint64_t ad, uint64_t bd, uint32_t en){
    asm volatile(
      "{\n\t.reg .pred p;\n\tsetp.ne.u32 p, %4, 0;\n\t"
      "tcgen05.mma.cta_group::1.kind::tf32 [%0], %1, %2, %3, {%5,%5,%5,%5}, p;\n\t}"
      :: "r"(d), "l"(ad), "l"(bd), "r"(IDESC_TF32), "r"(en), "r"(0u) : "memory");
}
__device__ __forceinline__ void tmem_alloc(uint32_t smem_dst, uint32_t ncols){
    asm volatile("tcgen05.alloc.cta_group::1.sync.aligned.shared::cta.b32 [%0], %1;"
                 :: "r"(smem_dst), "r"(ncols) : "memory");
}
__device__ __forceinline__ void tmem_dealloc(uint32_t tmem, uint32_t ncols){
    asm volatile("tcgen05.dealloc.cta_group::1.sync.aligned.b32 %0, %1;" :: "r"(tmem), "r"(ncols));
}
__device__ __forceinline__ void mma_commit(uint32_t mbar){
    asm volatile("tcgen05.commit.cta_group::1.mbarrier::arrive::one.shared::cluster.b64 [%0];"
                 :: "r"(mbar) : "memory");
}
__device__ __forceinline__ void mbar_init(uint32_t mbar, uint32_t cnt){
    asm volatile("mbarrier.init.shared.b64 [%0], %1;" :: "r"(mbar), "r"(cnt) : "memory");
}
__device__ __forceinline__ void mbar_wait(uint32_t mbar, uint32_t parity){
    asm volatile(
      "{\n\t.reg .pred P;\n\t"
      "W0_%=:\n\t"
      "mbarrier.try_wait.parity.acquire.cta.shared::cta.b64 P, [%0], %1, 0x989680;\n\t"
      "@P bra W1_%=;\n\t"
      "bra W0_%=;\n\t"
      "W1_%=:\n\t}"
      :: "r"(mbar), "r"(parity) : "memory");
}
__device__ __forceinline__ void fence_async_shared(){
    asm volatile("fence.proxy.async.shared::cta;" ::: "memory");
}
__device__ __forceinline__ void tc_fence_after(){
    asm volatile("tcgen05.fence::after_thread_sync;" ::: "memory");
}
__device__ __forceinline__ void tc_fence_before(){
    asm volatile("tcgen05.fence::before_thread_sync;" ::: "memory");
}
__device__ __forceinline__ void ldtm32(uint32_t* r, uint32_t tmem_addr){
    asm volatile(
        "tcgen05.ld.sync.aligned.32x32b.x32.b32 "
        "{%0, %1, %2, %3, %4, %5, %6, %7, %8, %9, %10, %11, %12, %13, %14, %15, "
        " %16, %17, %18, %19, %20, %21, %22, %23, %24, %25, %26, %27, %28, %29, %30, %31}, [%32];"
        : "=r"(r[0]),"=r"(r[1]),"=r"(r[2]),"=r"(r[3]),"=r"(r[4]),"=r"(r[5]),"=r"(r[6]),"=r"(r[7]),
          "=r"(r[8]),"=r"(r[9]),"=r"(r[10]),"=r"(r[11]),"=r"(r[12]),"=r"(r[13]),"=r"(r[14]),"=r"(r[15]),
          "=r"(r[16]),"=r"(r[17]),"=r"(r[18]),"=r"(r[19]),"=r"(r[20]),"=r"(r[21]),"=r"(r[22]),"=r"(r[23]),
          "=r"(r[24]),"=r"(r[25]),"=r"(r[26]),"=r"(r[27]),"=r"(r[28]),"=r"(r[29]),"=r"(r[30]),"=r"(r[31])
        : "r"(tmem_addr));
}
__device__ __forceinline__ void tmem_wait_ld(){
    asm volatile("tcgen05.wait::ld.sync.aligned;" ::: "memory");
}
#else
#define HAS_TC 0
#endif

// ---------------- kernel 0: zero output + counts ----------------
__global__ void k_zero(float4* __restrict__ out4){
    int i = blockIdx.x*blockDim.x + threadIdx.x;
    out4[i] = make_float4(0.f,0.f,0.f,0.f);
    if (i < NEXP) g_cnt[i] = 0;
}

// ---------------- kernel 1: router ----------------
__global__ void k_router(const float* __restrict__ x, const float* __restrict__ gw,
                         float* __restrict__ logits_out){
    int warp = (blockIdx.x*blockDim.x + threadIdx.x) >> 5;
    int lane = threadIdx.x & 31;
    if (warp >= TTOK) return;
    const float* xr = x + (size_t)warp*HDIM;
    float acc[NEXP];
    #pragma unroll
    for (int e=0;e<NEXP;e++) acc[e]=0.f;
    for (int i=lane;i<HDIM;i+=32){
        float xv = xr[i];
        #pragma unroll
        for (int e=0;e<NEXP;e++) acc[e] += xv * __ldg(&gw[e*HDIM+i]);
    }
    #pragma unroll
    for (int e=0;e<NEXP;e++){
        float v = acc[e];
        #pragma unroll
        for (int o=16;o>0;o>>=1) v += __shfl_xor_sync(0xffffffffu, v, o);
        acc[e]=v;
    }
    if (lane==0){
        float m = acc[0];
        #pragma unroll
        for (int e=1;e<NEXP;e++) m = fmaxf(m, acc[e]);
        float p[NEXP];
        #pragma unroll
        for (int e=0;e<NEXP;e++){ p[e] = expf(acc[e]-m); logits_out[(size_t)warp*NEXP+e] = acc[e]; }
        int i1 = 0;
        #pragma unroll
        for (int e=1;e<NEXP;e++) if (p[e] > p[i1]) i1 = e;
        int i2 = (i1==0)?1:0;
        #pragma unroll
        for (int e=0;e<NEXP;e++) if (e!=i1 && p[e] > p[i2]) i2 = e;
        float w1=p[i1], w2=p[i2], inv = 1.f/(w1+w2);
        g_tidx[warp*2+0]=i1; g_tw[warp*2+0]=w1*inv;
        g_tidx[warp*2+1]=i2; g_tw[warp*2+1]=w2*inv;
        atomicAdd(&g_cnt[i1],1);
        atomicAdd(&g_cnt[i2],1);
    }
}

// ---------------- kernel 2: scan ----------------
__global__ void k_scan(){
    if (threadIdx.x==0){
        int o=0;
        for (int e=0;e<NEXP;e++){ g_off[e]=o; g_cur[e]=o; o += g_cnt[e]; }
    }
}

// ---------------- kernel 3: placement ----------------
__global__ void k_place(){
    int t = blockIdx.x*blockDim.x + threadIdx.x;
    if (t >= TTOK) return;
    #pragma unroll
    for (int k=0;k<2;k++){
        int e = g_tidx[t*2+k];
        int pos = atomicAdd(&g_cur[e],1);
        g_tok[pos] = t;
        g_wt[pos]  = g_tw[t*2+k];
    }
}

// ================= GEMM 1: gate+up, fused SiLU =================
__global__ __launch_bounds__(256) __cluster_dims__(1,1,1) void k_gate_up(
        const float* __restrict__ x,
        const float* __restrict__ wg, const float* __restrict__ wu){
    extern __shared__ __align__(1024) char smem[];
    uint32_t sb = smem_u32(smem);

    int e   = blockIdx.z;
    int cnt = g_cnt[e];
    int m0  = blockIdx.x * BM;
    if (m0 >= cnt) return;
    int n0   = blockIdx.y * BN;
    int base = g_off[e];
    int tid  = threadIdx.x;
    int wid  = tid >> 5, lane = tid & 31;

#if HAS_TC
    // ---------------- tcgen05 path ----------------
    if (wid == 0) tmem_alloc(sb + 0, 128);      // Dg [0,64), Du [64,128)
    if (tid == 0){ mbar_init(sb+16, 1); mbar_init(sb+24, 1); }
    int* stok = (int*)(smem + 64);
    if (tid < BM){
        int r = m0 + tid;
        stok[tid] = (r < cnt) ? g_tok[base + r] : g_tok[base];
    }
    __syncthreads();
    uint32_t tmem = *(volatile uint32_t*)(smem + 0);

    const float* wgp = wg + (size_t)e*IDIM*HDIM + (size_t)n0*HDIM;
    const float* wup = wu + (size_t)e*IDIM*HDIM + (size_t)n0*HDIM;

    int ph0 = 0, ph1 = 0;
    const int NT = HDIM/BK;
    for (int t = 0; t < NT; t++){
        int s = t & 1;
        uint32_t mb = sb + 16 + s*8;
        if (t >= 2){
            if (s){ mbar_wait(mb, ph1); ph1 ^= 1; }
            else  { mbar_wait(mb, ph0); ph0 ^= 1; }
        }
        int kk = t * BK;
        char* As = smem + 2048         + s*16384;
        char* Bg = smem + 2048 + 32768 + s*8192;
        char* Bu = smem + 2048 + 49152 + s*8192;
        #pragma unroll
        for (int j=0;j<4;j++){
            int i = tid + j*256; int row = i>>3, c = i&7;
            float4 v = *(const float4*)(x + (size_t)stok[row]*HDIM + kk + c*4);
            v.x=tf32r(v.x); v.y=tf32r(v.y); v.z=tf32r(v.z); v.w=tf32r(v.w);
            *(float4*)(As + sw128(row*128 + c*16)) = v;
        }
        #pragma unroll
        for (int j=0;j<2;j++){
            int i = tid + j*256; int row = i>>3, c = i&7;
            float4 v = *(const float4*)(wgp + (size_t)row*HDIM + kk + c*4);
            v.x=tf32r(v.x); v.y=tf32r(v.y); v.z=tf32r(v.z); v.w=tf32r(v.w);
            *(float4*)(Bg + sw128(row*128 + c*16)) = v;
            float4 w = *(const float4*)(wup + (size_t)row*HDIM + kk + c*4);
            w.x=tf32r(w.x); w.y=tf32r(w.y); w.z=tf32r(w.z); w.w=tf32r(w.w);
            *(float4*)(Bu + sw128(row*128 + c*16)) = w;
        }
        __syncthreads();
        if (tid == 0){
            fence_async_shared();
            uint64_t ad  = make_desc(sb + 2048         + s*16384);
            uint64_t bgd = make_desc(sb + 2048 + 32768 + s*8192);
            uint64_t bud = make_desc(sb + 2048 + 49152 + s*8192);
            #pragma unroll
            for (int c8=0;c8<4;c8++){
                mma_tf32(tmem,      ad + 2*c8, bgd + 2*c8, (uint32_t)(t | c8));
                mma_tf32(tmem + 64, ad + 2*c8, bud + 2*c8, (uint32_t)(t | c8));
            }
            mma_commit(mb);
        }
    }
    mbar_wait(sb + 16, ph0);
    mbar_wait(sb + 24, ph1);
    tc_fence_after();
    {
        int half = wid >> 2, sub = wid & 3;
        int rloc = sub*32 + lane;
        int r    = m0 + rloc;
        uint32_t gv[32], uv[32];
        ldtm32(gv, tmem + half*32);
        ldtm32(uv, tmem + 64 + half*32);
        tmem_wait_ld();
        if (r < cnt){
            float o[32];
            #pragma unroll
            for (int j=0;j<32;j++){
                float g = __uint_as_float(gv[j]);
                float u = __uint_as_float(uv[j]);
                o[j] = g/(1.f+expf(-g))*u;
            }
            float* dst = g_act + (size_t)(base + r)*IDIM + n0 + half*32;
            #pragma unroll
            for (int j=0;j<8;j++)
                *(float4*)(dst + j*4) = make_float4(o[j*4],o[j*4+1],o[j*4+2],o[j*4+3]);
        }
    }
    tc_fence_before();
    __syncthreads();
    if (wid == 0) tmem_dealloc(tmem, 128);
#else
    // ---------------- legacy mma.sync + ldmatrix path ----------------
    const uint32_t OFF_A = 0, OFF_BG = 18432, OFF_BU = 27648;
    float (*As)[KP] = (float(*)[KP])(smem + OFF_A);
    float (*Bg)[KP] = (float(*)[KP])(smem + OFF_BG);
    float (*Bu)[KP] = (float(*)[KP])(smem + OFF_BU);
    int* stok = (int*)(smem + 36864);

    if (tid < BM){
        int r = m0 + tid;
        stok[tid] = (r < cnt) ? g_tok[base + r] : g_tok[base];
    }
    __syncthreads();

    const float* wgp = wg + (size_t)e*IDIM*HDIM;
    const float* wup = wu + (size_t)e*IDIM*HDIM;

    float cg[2][4][4], cu[2][4][4];
    #pragma unroll
    for (int mi=0;mi<2;mi++)
        #pragma unroll
        for (int ni=0;ni<4;ni++)
            #pragma unroll
            for (int q=0;q<4;q++){ cg[mi][ni][q]=0.f; cu[mi][ni][q]=0.f; }

    int wm = (wid&3)*32, wn = (wid>>2)*32;
    int lr = lane & 7, sel = lane >> 3;
    uint32_t aoff[2], bgoff[2], buoff[2];
    #pragma unroll
    for (int mi=0;mi<2;mi++){
        int row = wm + mi*16 + (sel&1)*8 + lr;
        int c0  = (sel>>1)*4;
        aoff[mi] = sb + OFF_A + (uint32_t)(row*KP + c0)*4u;
    }
    #pragma unroll
    for (int nq=0;nq<2;nq++){
        int row = wn + nq*16 + (sel>>1)*8 + lr;
        int c0  = (sel&1)*4;
        bgoff[nq] = sb + OFF_BG + (uint32_t)(row*KP + c0)*4u;
        buoff[nq] = sb + OFF_BU + (uint32_t)(row*KP + c0)*4u;
    }

    float4 ra[4], rbg[2], rbu[2];
    #pragma unroll
    for (int j=0;j<4;j++){
        int i = tid + j*256; int row = i>>3, k4 = i&7;
        ra[j] = *(const float4*)(&x[(size_t)stok[row]*HDIM + k4*4]);
    }
    #pragma unroll
    for (int j=0;j<2;j++){
        int i = tid + j*256; int n = i>>3, k4 = i&7;
        rbg[j] = *(const float4*)(&wgp[(size_t)(n0+n)*HDIM + k4*4]);
        rbu[j] = *(const float4*)(&wup[(size_t)(n0+n)*HDIM + k4*4]);
    }
    #pragma unroll
    for (int j=0;j<4;j++){
        int i = tid + j*256; int row = i>>3, k4 = i&7;
        As[row][k4*4+0]=tf32r(ra[j].x); As[row][k4*4+1]=tf32r(ra[j].y);
        As[row][k4*4+2]=tf32r(ra[j].z); As[row][k4*4+3]=tf32r(ra[j].w);
    }
    #pragma unroll
    for (int j=0;j<2;j++){
        int i = tid + j*256; int n = i>>3, k4 = i&7;
        Bg[n][k4*4+0]=tf32r(rbg[j].x); Bg[n][k4*4+1]=tf32r(rbg[j].y);
        Bg[n][k4*4+2]=tf32r(rbg[j].z); Bg[n][k4*4+3]=tf32r(rbg[j].w);
        Bu[n][k4*4+0]=tf32r(rbu[j].x); Bu[n][k4*4+1]=tf32r(rbu[j].y);
        Bu[n][k4*4+2]=tf32r(rbu[j].z); Bu[n][k4*4+3]=tf32r(rbu[j].w);
    }
    __syncthreads();

    for (int kk = BK; kk <= HDIM; kk += BK){
        bool more = (kk < HDIM);
        if (more){
            #pragma unroll
            for (int j=0;j<4;j++){
                int i = tid + j*256; int row = i>>3, k4 = i&7;
                ra[j] = *(const float4*)(&x[(size_t)stok[row]*HDIM + kk + k4*4]);
            }
            #pragma unroll
            for (int j=0;j<2;j++){
                int i = tid + j*256; int n = i>>3, k4 = i&7;
                rbg[j] = *(const float4*)(&wgp[(size_t)(n0+n)*HDIM + kk + k4*4]);
                rbu[j] = *(const float4*)(&wup[(size_t)(n0+n)*HDIM + kk + k4*4]);
            }
        }
        #pragma unroll
        for (int k8=0;k8<BK;k8+=8){
            uint32_t kb = (uint32_t)k8*4u;
            uint32_t a[2][4], bgf[2][4], buf[2][4];
            ldsm4(a[0],  aoff[0]  + kb);
            ldsm4(a[1],  aoff[1]  + kb);
            ldsm4(bgf[0], bgoff[0] + kb);
            ldsm4(bgf[1], bgoff[1] + kb);
            ldsm4(buf[0], buoff[0] + kb);
            ldsm4(buf[1], buoff[1] + kb);
            #pragma unroll
            for (int ni=0;ni<4;ni++){
                int q = ni>>1, ix = (ni&1)*2;
                #pragma unroll
                for (int mi=0;mi<2;mi++){
                    mma8(cg[mi][ni], a[mi], bgf[q][ix], bgf[q][ix+1]);
                    mma8(cu[mi][ni], a[mi], buf[q][ix], buf[q][ix+1]);
                }
            }
        }
        __syncthreads();
        if (more){
            #pragma unroll
            for (int j=0;j<4;j++){
                int i = tid + j*256; int row = i>>3, k4 = i&7;
                As[row][k4*4+0]=tf32r(ra[j].x); As[row][k4*4+1]=tf32r(ra[j].y);
                As[row][k4*4+2]=tf32r(ra[j].z); As[row][k4*4+3]=tf32r(ra[j].w);
            }
            #pragma unroll
            for (int j=0;j<2;j++){
                int i = tid + j*256; int n = i>>3, k4 = i&7;
                Bg[n][k4*4+0]=tf32r(rbg[j].x); Bg[n][k4*4+1]=tf32r(rbg[j].y);
                Bg[n][k4*4+2]=tf32r(rbg[j].z); Bg[n][k4*4+3]=tf32r(rbg[j].w);
                Bu[n][k4*4+0]=tf32r(rbu[j].x); Bu[n][k4*4+1]=tf32r(rbu[j].y);
                Bu[n][k4*4+2]=tf32r(rbu[j].z); Bu[n][k4*4+3]=tf32r(rbu[j].w);
            }
            __syncthreads();
        }
    }

    int grp = lane>>2, thr = lane&3;
    #pragma unroll
    for (int mi=0;mi<2;mi++){
        #pragma unroll
        for (int ni=0;ni<4;ni++){
            int ncol = n0 + wn + ni*8 + 2*thr;
            #pragma unroll
            for (int h=0;h<2;h++){
                int r = m0 + wm + mi*16 + grp + h*8;
                if (r < cnt){
                    size_t ro = (size_t)(base + r)*IDIM;
                    float g0 = cg[mi][ni][h*2+0], g1 = cg[mi][ni][h*2+1];
                    float u0 = cu[mi][ni][h*2+0], u1 = cu[mi][ni][h*2+1];
                    g_act[ro + ncol  ] = g0/(1.f+expf(-g0))*u0;
                    g_act[ro + ncol+1] = g1/(1.f+expf(-g1))*u1;
                }
            }
        }
    }
#endif
}

// ================= GEMM 2: down + weighted scatter =================
__global__ __launch_bounds__(256) __cluster_dims__(1,1,1) void k_down(
        const float* __restrict__ wd, float* __restrict__ out){
    extern __shared__ __align__(1024) char smem[];
    uint32_t sb = smem_u32(smem);

    int e   = blockIdx.z;
    int cnt = g_cnt[e];
    int m0  = blockIdx.x * BM;
    if (m0 >= cnt) return;
    int n0   = blockIdx.y * BN;
    int base = g_off[e];
    int tid  = threadIdx.x;
    int wid  = tid >> 5, lane = tid & 31;

#if HAS_TC
    if (wid == 0) tmem_alloc(sb + 0, 64);
    if (tid == 0){ mbar_init(sb+16, 1); mbar_init(sb+24, 1); }
    int*   stok = (int*)(smem + 64);
    float* swt  = (float*)(smem + 576);
    if (tid < BM){
        int r = m0 + tid;
        bool v = (r < cnt);
        stok[tid] = v ? g_tok[base + r] : 0;
        swt[tid]  = v ? g_wt[base + r] : 0.f;
    }
    __syncthreads();
    uint32_t tmem = *(volatile uint32_t*)(smem + 0);

    const float* wdp = wd + (size_t)e*HDIM*IDIM + (size_t)n0*IDIM;
    const float* ap  = g_act + (size_t)(base + m0)*IDIM;
    int rmax = cnt - m0;   // valid local rows in this tile (>=1)

    int ph0 = 0, ph1 = 0;
    const int NT = IDIM/BK;
    for (int t = 0; t < NT; t++){
        int s = t & 1;
        uint32_t mb = sb + 16 + s*8;
        if (t >= 2){
            if (s){ mbar_wait(mb, ph1); ph1 ^= 1; }
            else  { mbar_wait(mb, ph0); ph0 ^= 1; }
        }
        int kk = t * BK;
        char* As = smem + 2048         + s*16384;
        char* Bs = smem + 2048 + 32768 + s*8192;
        #pragma unroll
        for (int j=0;j<4;j++){
            int i = tid + j*256; int row = i>>3, c = i&7;
            int rr = (row < rmax) ? row : 0;            // clamp: no OOB read of g_act
            float4 v = *(const float4*)(ap + (size_t)rr*IDIM + kk + c*4);
            v.x=tf32r(v.x); v.y=tf32r(v.y); v.z=tf32r(v.z); v.w=tf32r(v.w);
            *(float4*)(As + sw128(row*128 + c*16)) = v;
        }
        #pragma unroll
        for (int j=0;j<2;j++){
            int i = tid + j*256; int row = i>>3, c = i&7;
            float4 v = *(const float4*)(wdp + (size_t)row*IDIM + kk + c*4);
            v.x=tf32r(v.x); v.y=tf32r(v.y); v.z=tf32r(v.z); v.w=tf32r(v.w);
            *(float4*)(Bs + sw128(row*128 + c*16)) = v;
        }
        __syncthreads();
        if (tid == 0){
            fence_async_shared();
            uint64_t ad = make_desc(sb + 2048         + s*16384);
            uint64_t bd = make_desc(sb + 2048 + 32768 + s*8192);
            #pragma unroll
            for (int c8=0;c8<4;c8++)
                mma_tf32(tmem, ad + 2*c8, bd + 2*c8, (uint32_t)(t | c8));
            mma_commit(mb);
        }
    }
    mbar_wait(sb + 16, ph0);
    mbar_wait(sb + 24, ph1);
    tc_fence_after();
    {
        int half = wid >> 2, sub = wid & 3;
        int rloc = sub*32 + lane;
        int r    = m0 + rloc;
        float w  = swt[rloc];
        int tok  = stok[rloc];
        uint32_t dv[32];
        ldtm32(dv, tmem + half*32);
        tmem_wait_ld();
        if (r < cnt){
            float* dst = out + (size_t)tok*HDIM + n0 + half*32;
            #pragma unroll
            for (int j=0;j<32;j++)
                atomicAdd(dst + j, __uint_as_float(dv[j]) * w);
        }
    }
    tc_fence_before();
    __syncthreads();
    if (wid == 0) tmem_dealloc(tmem, 64);
#else
    const uint32_t OFF_A = 0, OFF_B = 18432;
    float (*As)[KP] = (float(*)[KP])(smem + OFF_A);
    float (*Bs)[KP] = (float(*)[KP])(smem + OFF_B);
    int*   stok = (int*)(smem + 27648);
    float* swt  = (float*)(smem + 28160);

    if (tid < BM){
        int r = m0 + tid;
        bool v = (r < cnt);
        stok[tid] = v ? g_tok[base + r] : 0;
        swt[tid]  = v ? g_wt[base + r] : 0.f;
    }
    __syncthreads();

    const float* wdp = wd + (size_t)e*HDIM*IDIM;

    float cc[2][4][4];
    #pragma unroll
    for (int mi=0;mi<2;mi++)
        #pragma unroll
        for (int ni=0;ni<4;ni++)
            #pragma unroll
            for (int q=0;q<4;q++) cc[mi][ni][q]=0.f;

    int wm = (wid&3)*32, wn = (wid>>2)*32;
    int lr = lane & 7, sel = lane >> 3;
    uint32_t aoff[2], boff[2];
    #pragma unroll
    for (int mi=0;mi<2;mi++){
        int row = wm + mi*16 + (sel&1)*8 + lr;
        int c0  = (sel>>1)*4;
        aoff[mi] = sb + OFF_A + (uint32_t)(row*KP + c0)*4u;
    }
    #pragma unroll
    for (int nq=0;nq<2;nq++){
        int row = wn + nq*16 + (sel>>1)*8 + lr;
        int c0  = (sel&1)*4;
        boff[nq] = sb + OFF_B + (uint32_t)(row*KP + c0)*4u;
    }

    float4 ra[4], rb[2];
    #pragma unroll
    for (int j=0;j<4;j++){
        int i = tid + j*256; int row = i>>3, k4 = i&7;
        int rr = m0 + row; if (rr >= cnt) rr = m0;
        ra[j] = *(const float4*)(&g_act[(size_t)(base+rr)*IDIM + k4*4]);
    }
    #pragma unroll
    for (int j=0;j<2;j++){
        int i = tid + j*256; int n = i>>3, k4 = i&7;
        rb[j] = *(const float4*)(&wdp[(size_t)(n0+n)*IDIM + k4*4]);
    }
    #pragma unroll
    for (int j=0;j<4;j++){
        int i = tid + j*256; int row = i>>3, k4 = i&7;
        As[row][k4*4+0]=tf32r(ra[j].x); As[row][k4*4+1]=tf32r(ra[j].y);
        As[row][k4*4+2]=tf32r(ra[j].z); As[row][k4*4+3]=tf32r(ra[j].w);
    }
    #pragma unroll
    for (int j=0;j<2;j++){
        int i = tid + j*256; int n = i>>3, k4 = i&7;
        Bs[n][k4*4+0]=tf32r(rb[j].x); Bs[n][k4*4+1]=tf32r(rb[j].y);
        Bs[n][k4*4+2]=tf32r(rb[j].z); Bs[n][k4*4+3]=tf32r(rb[j].w);
    }
    __syncthreads();

    for (int kk = BK; kk <= IDIM; kk += BK){
        bool more = (kk < IDIM);
        if (more){
            #pragma unroll
            for (int j=0;j<4;j++){
                int i = tid + j*256; int row = i>>3, k4 = i&7;
                int rr = m0 + row; if (rr >= cnt) rr = m0;
                ra[j] = *(const float4*)(&g_act[(size_t)(base+rr)*IDIM + kk + k4*4]);
            }
            #pragma unroll
            for (int j=0;j<2;j++){
                int i = tid + j*256; int n = i>>3, k4 = i&7;
                rb[j] = *(const float4*)(&wdp[(size_t)(n0+n)*IDIM + kk + k4*4]);
            }
        }
        #pragma unroll
        for (int k8=0;k8<BK;k8+=8){
            uint32_t kb = (uint32_t)k8*4u;
            uint32_t a[2][4], bf[2][4];
            ldsm4(a[0], aoff[0] + kb);
            ldsm4(a[1], aoff[1] + kb);
            ldsm4(bf[0], boff[0] + kb);
            ldsm4(bf[1], boff[1] + kb);
            #pragma unroll
            for (int ni=0;ni<4;ni++){
                int q = ni>>1, ix = (ni&1)*2;
                #pragma unroll
                for (int mi=0;mi<2;mi++)
                    mma8(cc[mi][ni], a[mi], bf[q][ix], bf[q][ix+1]);
            }
        }
        __syncthreads();
        if (more){
            #pragma unroll
            for (int j=0;j<4;j++){
                int i = tid + j*256; int row = i>>3, k4 = i&7;
                As[row][k4*4+0]=tf32r(ra[j].x); As[row][k4*4+1]=tf32r(ra[j].y);
                As[row][k4*4+2]=tf32r(ra[j].z); As[row][k4*4+3]=tf32r(ra[j].w);
            }
            #pragma unroll
            for (int j=0;j<2;j++){
                int i = tid + j*256; int n = i>>3, k4 = i&7;
                Bs[n][k4*4+0]=tf32r(rb[j].x); Bs[n][k4*4+1]=tf32r(rb[j].y);
                Bs[n][k4*4+2]=tf32r(rb[j].z); Bs[n][k4*4+3]=tf32r(rb[j].w);
            }
            __syncthreads();
        }
    }

    int grp = lane>>2, thr = lane&3;
    #pragma unroll
    for (int mi=0;mi<2;mi++){
        #pragma unroll
        for (int ni=0;ni<4;ni++){
            int ncol = n0 + wn + ni*8 + 2*thr;
            #pragma unroll
            for (int h=0;h<2;h++){
                int rloc = wm + mi*16 + grp + h*8;
                int r = m0 + rloc;
                if (r < cnt){
                    float w = swt[rloc];
                    size_t o = (size_t)stok[rloc]*HDIM + ncol;
                    atomicAdd(&out[o  ], cc[mi][ni][h*2+0]*w);
                    atomicAdd(&out[o+1], cc[mi][ni][h*2+1]*w);
                }
            }
        }
    }
#endif
}

// ---------------- launch ----------------
extern "C" void kernel_launch(void* const* d_in, const int* in_sizes, int n_in,
                              void* d_out, int out_size){
    const float* x  = (const float*)d_in[0];
    const float* gw = (const float*)d_in[1];
    const float* wg = (const float*)d_in[2];
    const float* wu = (const float*)d_in[3];
    const float* wd = (const float*)d_in[4];
    float* out = (float*)d_out;

    cudaFuncSetAttribute(k_gate_up, cudaFuncAttributeMaxDynamicSharedMemorySize, GU_SMEM);
    cudaFuncSetAttribute(k_down,    cudaFuncAttributeMaxDynamicSharedMemorySize, DN_SMEM);

    k_zero<<<FINAL_ELEMS/4/256, 256>>>((float4*)out);
    k_router<<<TTOK/4, 128>>>(x, gw, out + FINAL_ELEMS);
    k_scan<<<1, 32>>>();
    k_place<<<TTOK/256, 256>>>();
    dim3 g1(TTOK/BM, IDIM/BN, NEXP);   // (32, 22, 8)
    k_gate_up<<<g1, 256, GU_SMEM>>>(x, wg, wu);
    dim3 g2(TTOK/BM, HDIM/BN, NEXP);   // (32, 32, 8)
    k_down<<<g2, 256, DN_SMEM>>>(wd, out);
}

// round 5
// speedup vs baseline: 2.1770x; 2.1770x over previous
#include <cuda_runtime.h>
#include <math.h>
#include <stdint.h>

#define TTOK 4096
#define HDIM 2048
#define IDIM 1408
#define NEXP 8
#define FINAL_ELEMS (TTOK*HDIM)
#define MAXROWS (TTOK*2)

#define BM 128
#define BNT 128        // TC-path N tile
#define BK 32
#define KP 36          // legacy-path smem row stride

#define GU_SMEM 100352
#define DN_SMEM 67584

// ---------------- scratch ----------------
__device__ int   g_cnt[NEXP];
__device__ int   g_off[NEXP];
__device__ int   g_cur[NEXP];
__device__ int   g_tok[MAXROWS];
__device__ float g_wt [MAXROWS];
__device__ int   g_tidx[TTOK*2];
__device__ float g_tw  [TTOK*2];
__device__ float g_act[(size_t)MAXROWS*IDIM];

// ---------------- common helpers ----------------
__device__ __forceinline__ uint32_t smem_u32(const void* p){
    uint32_t a;
    asm("{ .reg .u64 t; cvta.to.shared.u64 t, %1; cvt.u32.u64 %0, t; }" : "=r"(a) : "l"(p));
    return a;
}
__device__ __forceinline__ float tf32r(float f){
    unsigned u; asm("cvt.rna.tf32.f32 %0, %1;" : "=r"(u) : "f"(f));
    return __uint_as_float(u);
}
__device__ __forceinline__ void mma8(float* c, const uint32_t* a, uint32_t b0, uint32_t b1){
    asm volatile(
      "mma.sync.aligned.m16n8k8.row.col.f32.tf32.tf32.f32 "
      "{%0,%1,%2,%3},{%4,%5,%6,%7},{%8,%9},{%0,%1,%2,%3};\n"
      : "+f"(c[0]),"+f"(c[1]),"+f"(c[2]),"+f"(c[3])
      : "r"(a[0]),"r"(a[1]),"r"(a[2]),"r"(a[3]),"r"(b0),"r"(b1));
}
__device__ __forceinline__ void ldsm4(uint32_t* d, uint32_t addr){
    asm volatile("ldmatrix.sync.aligned.m8n8.x4.shared.b16 {%0,%1,%2,%3}, [%4];"
      : "=r"(d[0]),"=r"(d[1]),"=r"(d[2]),"=r"(d[3]) : "r"(addr));
}

#if defined(__CUDA_ARCH_FEAT_SM103_ALL) || defined(__CUDA_ARCH_FEAT_SM100_ALL)
#define HAS_TC 1
__device__ __forceinline__ uint32_t sw128(uint32_t off){ return off ^ ((off >> 3) & 0x70u); }
static __device__ __forceinline__ uint64_t make_desc(uint32_t smem_addr){
    const uint64_t base = (uint64_t(2) << 61) | (uint64_t(1) << 46) |
                          (uint64_t(64) << 32) | (uint64_t(1) << 16);
    return base | ((uint64_t)(smem_addr >> 4) & 0x3FFFu);
}
#define IDESC_TF32 ((1u<<4) | (2u<<7) | (2u<<10) | ((BNT/8u)<<17) | ((BM/16u)<<24))
__device__ __forceinline__ void mma_tf32(uint32_t d, uint64_t ad, uint64_t bd, uint32_t en){
    asm volatile(
      "{\n\t.reg .pred p;\n\tsetp.ne.u32 p, %4, 0;\n\t"
      "tcgen05.mma.cta_group::1.kind::tf32 [%0], %1, %2, %3, {%5,%5,%5,%5}, p;\n\t}"
      :: "r"(d), "l"(ad), "l"(bd), "r"(IDESC_TF32), "r"(en), "r"(0u) : "memory");
}
__device__ __forceinline__ void tmem_alloc(uint32_t smem_dst, uint32_t ncols){
    asm volatile("tcgen05.alloc.cta_group::1.sync.aligned.shared::cta.b32 [%0], %1;"
                 :: "r"(smem_dst), "r"(ncols) : "memory");
}
__device__ __forceinline__ void tmem_dealloc(uint32_t tmem, uint32_t ncols){
    asm volatile("tcgen05.dealloc.cta_group::1.sync.aligned.b32 %0, %1;" :: "r"(tmem), "r"(ncols));
}
__device__ __forceinline__ void mma_commit(uint32_t mbar){
    asm volatile("tcgen05.commit.cta_group::1.mbarrier::arrive::one.shared::cluster.b64 [%0];"
                 :: "r"(mbar) : "memory");
}
__device__ __forceinline__ void mbar_init(uint32_t mbar, uint32_t cnt){
    asm volatile("mbarrier.init.shared.b64 [%0], %1;" :: "r"(mbar), "r"(cnt) : "memory");
}
__device__ __forceinline__ void mbar_wait(uint32_t mbar, uint32_t parity){
    asm volatile(
      "{\n\t.reg .pred P;\n\t"
      "W0_%=:\n\t"
      "mbarrier.try_wait.parity.acquire.cta.shared::cta.b64 P, [%0], %1, 0x989680;\n\t"
      "@P bra W1_%=;\n\t"
      "bra W0_%=;\n\t"
      "W1_%=:\n\t}"
      :: "r"(mbar), "r"(parity) : "memory");
}
__device__ __forceinline__ void fence_async_shared(){
    asm volatile("fence.proxy.async.shared::cta;" ::: "memory");
}
__device__ __forceinline__ void tc_fence_after(){
    asm volatile("tcgen05.fence::after_thread_sync;" ::: "memory");
}
__device__ __forceinline__ void tc_fence_before(){
    asm volatile("tcgen05.fence::before_thread_sync;" ::: "memory");
}
__device__ __forceinline__ void ldtm32(uint32_t* r, uint32_t tmem_addr){
    asm volatile(
        "tcgen05.ld.sync.aligned.32x32b.x32.b32 "
        "{%0, %1, %2, %3, %4, %5, %6, %7, %8, %9, %10, %11, %12, %13, %14, %15, "
        " %16, %17, %18, %19, %20, %21, %22, %23, %24, %25, %26, %27, %28, %29, %30, %31}, [%32];"
        : "=r"(r[0]),"=r"(r[1]),"=r"(r[2]),"=r"(r[3]),"=r"(r[4]),"=r"(r[5]),"=r"(r[6]),"=r"(r[7]),
          "=r"(r[8]),"=r"(r[9]),"=r"(r[10]),"=r"(r[11]),"=r"(r[12]),"=r"(r[13]),"=r"(r[14]),"=r"(r[15]),
          "=r"(r[16]),"=r"(r[17]),"=r"(r[18]),"=r"(r[19]),"=r"(r[20]),"=r"(r[21]),"=r"(r[22]),"=r"(r[23]),
          "=r"(r[24]),"=r"(r[25]),"=r"(r[26]),"=r"(r[27]),"=r"(r[28]),"=r"(r[29]),"=r"(r[30]),"=r"(r[31])
        : "r"(tmem_addr));
}
__device__ __forceinline__ void tmem_wait_ld(){
    asm volatile("tcgen05.wait::ld.sync.aligned;" ::: "memory");
}
#else
#define HAS_TC 0
#endif

// ---------------- kernel 0: zero output + counts ----------------
__global__ void k_zero(float4* __restrict__ out4){
    int i = blockIdx.x*blockDim.x + threadIdx.x;
    out4[i] = make_float4(0.f,0.f,0.f,0.f);
    if (i < NEXP) g_cnt[i] = 0;
}

// ---------------- kernel 1: router ----------------
__global__ void k_router(const float* __restrict__ x, const float* __restrict__ gw,
                         float* __restrict__ logits_out){
    int warp = (blockIdx.x*blockDim.x + threadIdx.x) >> 5;
    int lane = threadIdx.x & 31;
    if (warp >= TTOK) return;
    const float* xr = x + (size_t)warp*HDIM;
    float acc[NEXP];
    #pragma unroll
    for (int e=0;e<NEXP;e++) acc[e]=0.f;
    for (int i=lane;i<HDIM;i+=32){
        float xv = xr[i];
        #pragma unroll
        for (int e=0;e<NEXP;e++) acc[e] += xv * __ldg(&gw[e*HDIM+i]);
    }
    #pragma unroll
    for (int e=0;e<NEXP;e++){
        float v = acc[e];
        #pragma unroll
        for (int o=16;o>0;o>>=1) v += __shfl_xor_sync(0xffffffffu, v, o);
        acc[e]=v;
    }
    if (lane==0){
        float m = acc[0];
        #pragma unroll
        for (int e=1;e<NEXP;e++) m = fmaxf(m, acc[e]);
        float p[NEXP];
        #pragma unroll
        for (int e=0;e<NEXP;e++){ p[e] = expf(acc[e]-m); logits_out[(size_t)warp*NEXP+e] = acc[e]; }
        int i1 = 0;
        #pragma unroll
        for (int e=1;e<NEXP;e++) if (p[e] > p[i1]) i1 = e;
        int i2 = (i1==0)?1:0;
        #pragma unroll
        for (int e=0;e<NEXP;e++) if (e!=i1 && p[e] > p[i2]) i2 = e;
        float w1=p[i1], w2=p[i2], inv = 1.f/(w1+w2);
        g_tidx[warp*2+0]=i1; g_tw[warp*2+0]=w1*inv;
        g_tidx[warp*2+1]=i2; g_tw[warp*2+1]=w2*inv;
        atomicAdd(&g_cnt[i1],1);
        atomicAdd(&g_cnt[i2],1);
    }
}

// ---------------- kernel 2: scan ----------------
__global__ void k_scan(){
    if (threadIdx.x==0){
        int o=0;
        for (int e=0;e<NEXP;e++){ g_off[e]=o; g_cur[e]=o; o += g_cnt[e]; }
    }
}

// ---------------- kernel 3: placement ----------------
__global__ void k_place(){
    int t = blockIdx.x*blockDim.x + threadIdx.x;
    if (t >= TTOK) return;
    #pragma unroll
    for (int k=0;k<2;k++){
        int e = g_tidx[t*2+k];
        int pos = atomicAdd(&g_cur[e],1);
        g_tok[pos] = t;
        g_wt[pos]  = g_tw[t*2+k];
    }
}

// ================= GEMM 1: gate+up, fused SiLU =================
__global__ __launch_bounds__(256,2) __cluster_dims__(1,1,1) void k_gate_up(
        const float* __restrict__ x,
        const float* __restrict__ wg, const float* __restrict__ wu){
    extern __shared__ __align__(1024) char smem[];
    uint32_t sb = smem_u32(smem);

    int e   = blockIdx.z;
    int cnt = g_cnt[e];
    int m0  = blockIdx.x * BM;
    if (m0 >= cnt) return;
    int base = g_off[e];
    int tid  = threadIdx.x;
    int wid  = tid >> 5, lane = tid & 31;

#if HAS_TC
    // ------------- tcgen05 path, BN=128, prefetched pipeline -------------
    int n0 = blockIdx.y * BNT;
    if (wid == 0) tmem_alloc(sb + 0, 256);      // Dg [0,128), Du [128,256)
    if (tid == 0){ mbar_init(sb+16, 1); mbar_init(sb+24, 1); }
    int* stok = (int*)(smem + 64);
    if (tid < BM){
        int r = m0 + tid;
        stok[tid] = (r < cnt) ? g_tok[base + r] : g_tok[base];
    }
    __syncthreads();
    uint32_t tmem = *(volatile uint32_t*)(smem + 0);

    const float* wgp = wg + (size_t)e*IDIM*HDIM + (size_t)n0*HDIM;
    const float* wup = wu + (size_t)e*IDIM*HDIM + (size_t)n0*HDIM;

    // per-thread load indices: i = tid + j*256; row = i>>3, c = i&7
    int lrow = tid >> 3, lc = (tid & 7) * 4;

    float4 ra[4], rbg[4], rbu[4];
    // prologue: fetch tile 0 into regs
    #pragma unroll
    for (int j=0;j<4;j++){
        int row = lrow + j*32;
        ra[j]  = *(const float4*)(x   + (size_t)stok[row]*HDIM + lc);
        rbg[j] = *(const float4*)(wgp + (size_t)row*HDIM + lc);
        rbu[j] = *(const float4*)(wup + (size_t)row*HDIM + lc);
    }

    int ph0 = 0, ph1 = 0;
    const int NT = HDIM/BK;
    for (int t = 0; t < NT; t++){
        int s = t & 1;
        uint32_t mb = sb + 16 + s*8;
        if (t >= 2){
            if (s){ mbar_wait(mb, ph1); ph1 ^= 1; }
            else  { mbar_wait(mb, ph0); ph0 ^= 1; }
        }
        char* As = smem + 2048         + s*16384;
        char* Bg = smem + 2048 + 32768 + s*16384;
        char* Bu = smem + 2048 + 49152 + s*16384;   // NOTE: Bg stages [34816..67584) ; recompute below
        // correct stage bases:
        As = smem + 2048          + s*16384;
        Bg = smem + 2048 + 32768  + s*16384;
        Bu = smem + 2048 + 65536  + s*16384;
        #pragma unroll
        for (int j=0;j<4;j++){
            int row = lrow + j*32;
            float4 v = ra[j];
            v.x=tf32r(v.x); v.y=tf32r(v.y); v.z=tf32r(v.z); v.w=tf32r(v.w);
            *(float4*)(As + sw128(row*128 + lc*4)) = v;
            v = rbg[j];
            v.x=tf32r(v.x); v.y=tf32r(v.y); v.z=tf32r(v.z); v.w=tf32r(v.w);
            *(float4*)(Bg + sw128(row*128 + lc*4)) = v;
            v = rbu[j];
            v.x=tf32r(v.x); v.y=tf32r(v.y); v.z=tf32r(v.z); v.w=tf32r(v.w);
            *(float4*)(Bu + sw128(row*128 + lc*4)) = v;
        }
        __syncthreads();
        if (tid == 0){
            fence_async_shared();
            uint64_t ad  = make_desc(sb + 2048         + s*16384);
            uint64_t bgd = make_desc(sb + 2048 + 32768 + s*16384);
            uint64_t bud = make_desc(sb + 2048 + 65536 + s*16384);
            #pragma unroll
            for (int c8=0;c8<4;c8++){
                mma_tf32(tmem,       ad + 2*c8, bgd + 2*c8, (uint32_t)(t | c8));
                mma_tf32(tmem + 128, ad + 2*c8, bud + 2*c8, (uint32_t)(t | c8));
            }
            mma_commit(mb);
        }
        // prefetch tile t+1 while MMA t runs
        if (t + 1 < NT){
            int kk = (t+1) * BK;
            #pragma unroll
            for (int j=0;j<4;j++){
                int row = lrow + j*32;
                ra[j]  = *(const float4*)(x   + (size_t)stok[row]*HDIM + kk + lc);
                rbg[j] = *(const float4*)(wgp + (size_t)row*HDIM + kk + lc);
                rbu[j] = *(const float4*)(wup + (size_t)row*HDIM + kk + lc);
            }
        }
    }
    mbar_wait(sb + 16, ph0);
    mbar_wait(sb + 24, ph1);
    tc_fence_after();
    {
        int half = wid >> 2, sub = wid & 3;
        int rloc = sub*32 + lane;
        int r    = m0 + rloc;
        #pragma unroll
        for (int it=0; it<2; it++){
            int cb = half*64 + it*32;
            uint32_t gv[32], uv[32];
            ldtm32(gv, tmem + cb);
            ldtm32(uv, tmem + 128 + cb);
            tmem_wait_ld();
            if (r < cnt){
                float o[32];
                #pragma unroll
                for (int j=0;j<32;j++){
                    float g = __uint_as_float(gv[j]);
                    float u = __uint_as_float(uv[j]);
                    o[j] = g/(1.f+expf(-g))*u;
                }
                float* dst = g_act + (size_t)(base + r)*IDIM + n0 + cb;
                #pragma unroll
                for (int j=0;j<8;j++)
                    *(float4*)(dst + j*4) = make_float4(o[j*4],o[j*4+1],o[j*4+2],o[j*4+3]);
            }
        }
    }
    tc_fence_before();
    __syncthreads();
    if (wid == 0) tmem_dealloc(tmem, 256);
#else
    // ------------- legacy mma.sync + ldmatrix path (PTX-pass fallback) -------------
    const uint32_t OFF_A = 0, OFF_BG = 18432, OFF_BU = 27648;
    float (*As)[KP] = (float(*)[KP])(smem + OFF_A);
    float (*Bg)[KP] = (float(*)[KP])(smem + OFF_BG);
    float (*Bu)[KP] = (float(*)[KP])(smem + OFF_BU);
    int* stok = (int*)(smem + 36864);

    if (tid < BM){
        int r = m0 + tid;
        stok[tid] = (r < cnt) ? g_tok[base + r] : g_tok[base];
    }
    __syncthreads();

    const float* wgp = wg + (size_t)e*IDIM*HDIM;
    const float* wup = wu + (size_t)e*IDIM*HDIM;

    int wm = (wid&3)*32, wn = (wid>>2)*32;
    int lr = lane & 7, sel = lane >> 3;
    uint32_t aoff[2], bgoff[2], buoff[2];
    #pragma unroll
    for (int mi=0;mi<2;mi++){
        int row = wm + mi*16 + (sel&1)*8 + lr;
        int c0  = (sel>>1)*4;
        aoff[mi] = sb + OFF_A + (uint32_t)(row*KP + c0)*4u;
    }
    #pragma unroll
    for (int nq=0;nq<2;nq++){
        int row = wn + nq*16 + (sel>>1)*8 + lr;
        int c0  = (sel&1)*4;
        bgoff[nq] = sb + OFF_BG + (uint32_t)(row*KP + c0)*4u;
        buoff[nq] = sb + OFF_BU + (uint32_t)(row*KP + c0)*4u;
    }

    for (int hpass = 0; hpass < 2; hpass++){
        int n0 = blockIdx.y * BNT + hpass*64;
        __syncthreads();

        float cg[2][4][4], cu[2][4][4];
        #pragma unroll
        for (int mi=0;mi<2;mi++)
            #pragma unroll
            for (int ni=0;ni<4;ni++)
                #pragma unroll
                for (int q=0;q<4;q++){ cg[mi][ni][q]=0.f; cu[mi][ni][q]=0.f; }

        float4 ra[4], rbg[2], rbu[2];
        #pragma unroll
        for (int j=0;j<4;j++){
            int i = tid + j*256; int row = i>>3, k4 = i&7;
            ra[j] = *(const float4*)(&x[(size_t)stok[row]*HDIM + k4*4]);
        }
        #pragma unroll
        for (int j=0;j<2;j++){
            int i = tid + j*256; int n = i>>3, k4 = i&7;
            rbg[j] = *(const float4*)(&wgp[(size_t)(n0+n)*HDIM + k4*4]);
            rbu[j] = *(const float4*)(&wup[(size_t)(n0+n)*HDIM + k4*4]);
        }
        #pragma unroll
        for (int j=0;j<4;j++){
            int i = tid + j*256; int row = i>>3, k4 = i&7;
            As[row][k4*4+0]=tf32r(ra[j].x); As[row][k4*4+1]=tf32r(ra[j].y);
            As[row][k4*4+2]=tf32r(ra[j].z); As[row][k4*4+3]=tf32r(ra[j].w);
        }
        #pragma unroll
        for (int j=0;j<2;j++){
            int i = tid + j*256; int n = i>>3, k4 = i&7;
            Bg[n][k4*4+0]=tf32r(rbg[j].x); Bg[n][k4*4+1]=tf32r(rbg[j].y);
            Bg[n][k4*4+2]=tf32r(rbg[j].z); Bg[n][k4*4+3]=tf32r(rbg[j].w);
            Bu[n][k4*4+0]=tf32r(rbu[j].x); Bu[n][k4*4+1]=tf32r(rbu[j].y);
            Bu[n][k4*4+2]=tf32r(rbu[j].z); Bu[n][k4*4+3]=tf32r(rbu[j].w);
        }
        __syncthreads();

        for (int kk = BK; kk <= HDIM; kk += BK){
            bool more = (kk < HDIM);
            if (more){
                #pragma unroll
                for (int j=0;j<4;j++){
                    int i = tid + j*256; int row = i>>3, k4 = i&7;
                    ra[j] = *(const float4*)(&x[(size_t)stok[row]*HDIM + kk + k4*4]);
                }
                #pragma unroll
                for (int j=0;j<2;j++){
                    int i = tid + j*256; int n = i>>3, k4 = i&7;
                    rbg[j] = *(const float4*)(&wgp[(size_t)(n0+n)*HDIM + kk + k4*4]);
                    rbu[j] = *(const float4*)(&wup[(size_t)(n0+n)*HDIM + kk + k4*4]);
                }
            }
            #pragma unroll
            for (int k8=0;k8<BK;k8+=8){
                uint32_t kb = (uint32_t)k8*4u;
                uint32_t a[2][4], bgf[2][4], buf[2][4];
                ldsm4(a[0],  aoff[0]  + kb);
                ldsm4(a[1],  aoff[1]  + kb);
                ldsm4(bgf[0], bgoff[0] + kb);
                ldsm4(bgf[1], bgoff[1] + kb);
                ldsm4(buf[0], buoff[0] + kb);
                ldsm4(buf[1], buoff[1] + kb);
                #pragma unroll
                for (int ni=0;ni<4;ni++){
                    int q = ni>>1, ix = (ni&1)*2;
                    #pragma unroll
                    for (int mi=0;mi<2;mi++){
                        mma8(cg[mi][ni], a[mi], bgf[q][ix], bgf[q][ix+1]);
                        mma8(cu[mi][ni], a[mi], buf[q][ix], buf[q][ix+1]);
                    }
                }
            }
            __syncthreads();
            if (more){
                #pragma unroll
                for (int j=0;j<4;j++){
                    int i = tid + j*256; int row = i>>3, k4 = i&7;
                    As[row][k4*4+0]=tf32r(ra[j].x); As[row][k4*4+1]=tf32r(ra[j].y);
                    As[row][k4*4+2]=tf32r(ra[j].z); As[row][k4*4+3]=tf32r(ra[j].w);
                }
                #pragma unroll
                for (int j=0;j<2;j++){
                    int i = tid + j*256; int n = i>>3, k4 = i&7;
                    Bg[n][k4*4+0]=tf32r(rbg[j].x); Bg[n][k4*4+1]=tf32r(rbg[j].y);
                    Bg[n][k4*4+2]=tf32r(rbg[j].z); Bg[n][k4*4+3]=tf32r(rbg[j].w);
                    Bu[n][k4*4+0]=tf32r(rbu[j].x); Bu[n][k4*4+1]=tf32r(rbu[j].y);
                    Bu[n][k4*4+2]=tf32r(rbu[j].z); Bu[n][k4*4+3]=tf32r(rbu[j].w);
                }
                __syncthreads();
            }
        }

        int grp = lane>>2, thr = lane&3;
        #pragma unroll
        for (int mi=0;mi<2;mi++){
            #pragma unroll
            for (int ni=0;ni<4;ni++){
                int ncol = n0 + wn + ni*8 + 2*thr;
                #pragma unroll
                for (int h=0;h<2;h++){
                    int r = m0 + wm + mi*16 + grp + h*8;
                    if (r < cnt){
                        size_t ro = (size_t)(base + r)*IDIM;
                        float g0 = cg[mi][ni][h*2+0], g1 = cg[mi][ni][h*2+1];
                        float u0 = cu[mi][ni][h*2+0], u1 = cu[mi][ni][h*2+1];
                        g_act[ro + ncol  ] = g0/(1.f+expf(-g0))*u0;
                        g_act[ro + ncol+1] = g1/(1.f+expf(-g1))*u1;
                    }
                }
            }
        }
    }
#endif
}

// ================= GEMM 2: down + weighted scatter =================
__global__ __launch_bounds__(256,2) __cluster_dims__(1,1,1) void k_down(
        const float* __restrict__ wd, float* __restrict__ out){
    extern __shared__ __align__(1024) char smem[];
    uint32_t sb = smem_u32(smem);

    int e   = blockIdx.z;
    int cnt = g_cnt[e];
    int m0  = blockIdx.x * BM;
    if (m0 >= cnt) return;
    int base = g_off[e];
    int tid  = threadIdx.x;
    int wid  = tid >> 5, lane = tid & 31;

#if HAS_TC
    int n0 = blockIdx.y * BNT;
    if (wid == 0) tmem_alloc(sb + 0, 128);
    if (tid == 0){ mbar_init(sb+16, 1); mbar_init(sb+24, 1); }
    int*   stok = (int*)(smem + 64);
    float* swt  = (float*)(smem + 576);
    if (tid < BM){
        int r = m0 + tid;
        bool v = (r < cnt);
        stok[tid] = v ? g_tok[base + r] : 0;
        swt[tid]  = v ? g_wt[base + r] : 0.f;
    }
    __syncthreads();
    uint32_t tmem = *(volatile uint32_t*)(smem + 0);

    const float* wdp = wd + (size_t)e*HDIM*IDIM + (size_t)n0*IDIM;
    const float* ap  = g_act + (size_t)(base + m0)*IDIM;
    int rmax = cnt - m0;

    int lrow = tid >> 3, lc = (tid & 7) * 4;
    int arow = (lrow < rmax) ? lrow : 0;     // clamped gather row for A (j-strided below)

    float4 ra[4], rb[4];
    #pragma unroll
    for (int j=0;j<4;j++){
        int row = lrow + j*32;
        int rr  = (row < rmax) ? row : 0;
        ra[j] = *(const float4*)(ap  + (size_t)rr*IDIM + lc);
        rb[j] = *(const float4*)(wdp + (size_t)row*IDIM + lc);
    }
    (void)arow;

    int ph0 = 0, ph1 = 0;
    const int NT = IDIM/BK;
    for (int t = 0; t < NT; t++){
        int s = t & 1;
        uint32_t mb = sb + 16 + s*8;
        if (t >= 2){
            if (s){ mbar_wait(mb, ph1); ph1 ^= 1; }
            else  { mbar_wait(mb, ph0); ph0 ^= 1; }
        }
        char* As = smem + 2048         + s*16384;
        char* Bs = smem + 2048 + 32768 + s*16384;
        #pragma unroll
        for (int j=0;j<4;j++){
            int row = lrow + j*32;
            float4 v = ra[j];
            v.x=tf32r(v.x); v.y=tf32r(v.y); v.z=tf32r(v.z); v.w=tf32r(v.w);
            *(float4*)(As + sw128(row*128 + lc*4)) = v;
            v = rb[j];
            v.x=tf32r(v.x); v.y=tf32r(v.y); v.z=tf32r(v.z); v.w=tf32r(v.w);
            *(float4*)(Bs + sw128(row*128 + lc*4)) = v;
        }
        __syncthreads();
        if (tid == 0){
            fence_async_shared();
            uint64_t ad = make_desc(sb + 2048         + s*16384);
            uint64_t bd = make_desc(sb + 2048 + 32768 + s*16384);
            #pragma unroll
            for (int c8=0;c8<4;c8++)
                mma_tf32(tmem, ad + 2*c8, bd + 2*c8, (uint32_t)(t | c8));
            mma_commit(mb);
        }
        if (t + 1 < NT){
            int kk = (t+1) * BK;
            #pragma unroll
            for (int j=0;j<4;j++){
                int row = lrow + j*32;
                int rr  = (row < rmax) ? row : 0;
                ra[j] = *(const float4*)(ap  + (size_t)rr*IDIM + kk + lc);
                rb[j] = *(const float4*)(wdp + (size_t)row*IDIM + kk + lc);
            }
        }
    }
    mbar_wait(sb + 16, ph0);
    mbar_wait(sb + 24, ph1);
    tc_fence_after();
    {
        int half = wid >> 2, sub = wid & 3;
        int rloc = sub*32 + lane;
        int r    = m0 + rloc;
        float w  = swt[rloc];
        int tok  = stok[rloc];
        #pragma unroll
        for (int it=0; it<2; it++){
            int cb = half*64 + it*32;
            uint32_t dv[32];
            ldtm32(dv, tmem + cb);
            tmem_wait_ld();
            if (r < cnt){
                float* dst = out + (size_t)tok*HDIM + n0 + cb;
                #pragma unroll
                for (int j=0;j<32;j++)
                    atomicAdd(dst + j, __uint_as_float(dv[j]) * w);
            }
        }
    }
    tc_fence_before();
    __syncthreads();
    if (wid == 0) tmem_dealloc(tmem, 128);
#else
    const uint32_t OFF_A = 0, OFF_B = 18432;
    float (*As)[KP] = (float(*)[KP])(smem + OFF_A);
    float (*Bs)[KP] = (float(*)[KP])(smem + OFF_B);
    int*   stok = (int*)(smem + 27648);
    float* swt  = (float*)(smem + 28160);

    if (tid < BM){
        int r = m0 + tid;
        bool v = (r < cnt);
        stok[tid] = v ? g_tok[base + r] : 0;
        swt[tid]  = v ? g_wt[base + r] : 0.f;
    }
    __syncthreads();

    const float* wdp = wd + (size_t)e*HDIM*IDIM;

    int wm = (wid&3)*32, wn = (wid>>2)*32;
    int lr = lane & 7, sel = lane >> 3;
    uint32_t aoff[2], boff[2];
    #pragma unroll
    for (int mi=0;mi<2;mi++){
        int row = wm + mi*16 + (sel&1)*8 + lr;
        int c0  = (sel>>1)*4;
        aoff[mi] = sb + OFF_A + (uint32_t)(row*KP + c0)*4u;
    }
    #pragma unroll
    for (int nq=0;nq<2;nq++){
        int row = wn + nq*16 + (sel>>1)*8 + lr;
        int c0  = (sel&1)*4;
        boff[nq] = sb + OFF_B + (uint32_t)(row*KP + c0)*4u;
    }

    for (int hpass = 0; hpass < 2; hpass++){
        int n0 = blockIdx.y * BNT + hpass*64;
        __syncthreads();

        float cc[2][4][4];
        #pragma unroll
        for (int mi=0;mi<2;mi++)
            #pragma unroll
            for (int ni=0;ni<4;ni++)
                #pragma unroll
                for (int q=0;q<4;q++) cc[mi][ni][q]=0.f;

        float4 ra[4], rb[2];
        #pragma unroll
        for (int j=0;j<4;j++){
            int i = tid + j*256; int row = i>>3, k4 = i&7;
            int rr = m0 + row; if (rr >= cnt) rr = m0;
            ra[j] = *(const float4*)(&g_act[(size_t)(base+rr)*IDIM + k4*4]);
        }
        #pragma unroll
        for (int j=0;j<2;j++){
            int i = tid + j*256; int n = i>>3, k4 = i&7;
            rb[j] = *(const float4*)(&wdp[(size_t)(n0+n)*IDIM + k4*4]);
        }
        #pragma unroll
        for (int j=0;j<4;j++){
            int i = tid + j*256; int row = i>>3, k4 = i&7;
            As[row][k4*4+0]=tf32r(ra[j].x); As[row][k4*4+1]=tf32r(ra[j].y);
            As[row][k4*4+2]=tf32r(ra[j].z); As[row][k4*4+3]=tf32r(ra[j].w);
        }
        #pragma unroll
        for (int j=0;j<2;j++){
            int i = tid + j*256; int n = i>>3, k4 = i&7;
            Bs[n][k4*4+0]=tf32r(rb[j].x); Bs[n][k4*4+1]=tf32r(rb[j].y);
            Bs[n][k4*4+2]=tf32r(rb[j].z); Bs[n][k4*4+3]=tf32r(rb[j].w);
        }
        __syncthreads();

        for (int kk = BK; kk <= IDIM; kk += BK){
            bool more = (kk < IDIM);
            if (more){
                #pragma unroll
                for (int j=0;j<4;j++){
                    int i = tid + j*256; int row = i>>3, k4 = i&7;
                    int rr = m0 + row; if (rr >= cnt) rr = m0;
                    ra[j] = *(const float4*)(&g_act[(size_t)(base+rr)*IDIM + kk + k4*4]);
                }
                #pragma unroll
                for (int j=0;j<2;j++){
                    int i = tid + j*256; int n = i>>3, k4 = i&7;
                    rb[j] = *(const float4*)(&wdp[(size_t)(n0+n)*IDIM + kk + k4*4]);
                }
            }
            #pragma unroll
            for (int k8=0;k8<BK;k8+=8){
                uint32_t kb = (uint32_t)k8*4u;
                uint32_t a[2][4], bf[2][4];
                ldsm4(a[0], aoff[0] + kb);
                ldsm4(a[1], aoff[1] + kb);
                ldsm4(bf[0], boff[0] + kb);
                ldsm4(bf[1], boff[1] + kb);
                #pragma unroll
                for (int ni=0;ni<4;ni++){
                    int q = ni>>1, ix = (ni&1)*2;
                    #pragma unroll
                    for (int mi=0;mi<2;mi++)
                        mma8(cc[mi][ni], a[mi], bf[q][ix], bf[q][ix+1]);
                }
            }
            __syncthreads();
            if (more){
                #pragma unroll
                for (int j=0;j<4;j++){
                    int i = tid + j*256; int row = i>>3, k4 = i&7;
                    As[row][k4*4+0]=tf32r(ra[j].x); As[row][k4*4+1]=tf32r(ra[j].y);
                    As[row][k4*4+2]=tf32r(ra[j].z); As[row][k4*4+3]=tf32r(ra[j].w);
                }
                #pragma unroll
                for (int j=0;j<2;j++){
                    int i = tid + j*256; int n = i>>3, k4 = i&7;
                    Bs[n][k4*4+0]=tf32r(rb[j].x); Bs[n][k4*4+1]=tf32r(rb[j].y);
                    Bs[n][k4*4+2]=tf32r(rb[j].z); Bs[n][k4*4+3]=tf32r(rb[j].w);
                }
                __syncthreads();
            }
        }

        int grp = lane>>2, thr = lane&3;
        #pragma unroll
        for (int mi=0;mi<2;mi++){
            #pragma unroll
            for (int ni=0;ni<4;ni++){
                int ncol = n0 + wn + ni*8 + 2*thr;
                #pragma unroll
                for (int h=0;h<2;h++){
                    int rloc = wm + mi*16 + grp + h*8;
                    int r = m0 + rloc;
                    if (r < cnt){
                        float w = swt[rloc];
                        size_t o = (size_t)stok[rloc]*HDIM + ncol;
                        atomicAdd(&out[o  ], cc[mi][ni][h*2+0]*w);
                        atomicAdd(&out[o+1], cc[mi][ni][h*2+1]*w);
                    }
                }
            }
        }
    }
#endif
}

// ---------------- launch ----------------
extern "C" void kernel_launch(void* const* d_in, const int* in_sizes, int n_in,
                              void* d_out, int out_size){
    const float* x  = (const float*)d_in[0];
    const float* gw = (const float*)d_in[1];
    const float* wg = (const float*)d_in[2];
    const float* wu = (const float*)d_in[3];
    const float* wd = (const float*)d_in[4];
    float* out = (float*)d_out;

    cudaFuncSetAttribute(k_gate_up, cudaFuncAttributeMaxDynamicSharedMemorySize, GU_SMEM);
    cudaFuncSetAttribute(k_down,    cudaFuncAttributeMaxDynamicSharedMemorySize, DN_SMEM);

    k_zero<<<FINAL_ELEMS/4/256, 256>>>((float4*)out);
    k_router<<<TTOK/4, 128>>>(x, gw, out + FINAL_ELEMS);
    k_scan<<<1, 32>>>();
    k_place<<<TTOK/256, 256>>>();
    dim3 g1(TTOK/BM, IDIM/BNT, NEXP);   // (32, 11, 8)
    k_gate_up<<<g1, 256, GU_SMEM>>>(x, wg, wu);
    dim3 g2(TTOK/BM, HDIM/BNT, NEXP);   // (32, 16, 8)
    k_down<<<g2, 256, DN_SMEM>>>(wd, out);
}

// round 6
// speedup vs baseline: 2.9692x; 1.3639x over previous
#include <cuda_runtime.h>
#include <math.h>
#include <stdint.h>

#define TTOK 4096
#define HDIM 2048
#define IDIM 1408
#define NEXP 8
#define FINAL_ELEMS (TTOK*HDIM)
#define MAXROWS (TTOK*2)

#define BMT 256        // TC-path M tile (2 x 128 MMAs)
#define BNT 128        // TC-path N tile
#define BK 32
#define KP 36          // legacy-path smem row stride

// TC smem layouts
#define GU_A_OFF 4096
#define GU_BG_OFF (4096 + 3*32768)            // 102400
#define GU_BU_OFF (GU_BG_OFF + 3*16384)       // 151552
#define GU_SMEM   (GU_BU_OFF + 3*16384)       // 200704
#define DN_A_OFF 4096
#define DN_B_OFF (4096 + 3*32768)             // 102400
#define DN_SMEM  (DN_B_OFF + 3*16384)         // 151552

// ---------------- scratch ----------------
__device__ int   g_cnt[NEXP];
__device__ int   g_off[NEXP];
__device__ int   g_cur[NEXP];
__device__ int   g_tok[MAXROWS];
__device__ float g_wt [MAXROWS];
__device__ int   g_tidx[TTOK*2];
__device__ float g_tw  [TTOK*2];
__device__ float g_act[(size_t)MAXROWS*IDIM];

// ---------------- common helpers ----------------
__device__ __forceinline__ uint32_t smem_u32(const void* p){
    uint32_t a;
    asm("{ .reg .u64 t; cvta.to.shared.u64 t, %1; cvt.u32.u64 %0, t; }" : "=r"(a) : "l"(p));
    return a;
}
__device__ __forceinline__ float tf32r(float f){
    unsigned u; asm("cvt.rna.tf32.f32 %0, %1;" : "=r"(u) : "f"(f));
    return __uint_as_float(u);
}
__device__ __forceinline__ void mma8(float* c, const uint32_t* a, uint32_t b0, uint32_t b1){
    asm volatile(
      "mma.sync.aligned.m16n8k8.row.col.f32.tf32.tf32.f32 "
      "{%0,%1,%2,%3},{%4,%5,%6,%7},{%8,%9},{%0,%1,%2,%3};\n"
      : "+f"(c[0]),"+f"(c[1]),"+f"(c[2]),"+f"(c[3])
      : "r"(a[0]),"r"(a[1]),"r"(a[2]),"r"(a[3]),"r"(b0),"r"(b1));
}
__device__ __forceinline__ void ldsm4(uint32_t* d, uint32_t addr){
    asm volatile("ldmatrix.sync.aligned.m8n8.x4.shared.b16 {%0,%1,%2,%3}, [%4];"
      : "=r"(d[0]),"=r"(d[1]),"=r"(d[2]),"=r"(d[3]) : "r"(addr));
}

#if defined(__CUDA_ARCH_FEAT_SM103_ALL) || defined(__CUDA_ARCH_FEAT_SM100_ALL)
#define HAS_TC 1
__device__ __forceinline__ uint32_t sw128(uint32_t off){ return off ^ ((off >> 3) & 0x70u); }
static __device__ __forceinline__ uint64_t make_desc(uint32_t smem_addr){
    const uint64_t base = (uint64_t(2) << 61) | (uint64_t(1) << 46) |
                          (uint64_t(64) << 32) | (uint64_t(1) << 16);
    return base | ((uint64_t)(smem_addr >> 4) & 0x3FFFu);
}
#define IDESC_TF32 ((1u<<4) | (2u<<7) | (2u<<10) | ((BNT/8u)<<17) | (8u<<24))
__device__ __forceinline__ void mma_tf32(uint32_t d, uint64_t ad, uint64_t bd, uint32_t en){
    asm volatile(
      "{\n\t.reg .pred p;\n\tsetp.ne.u32 p, %4, 0;\n\t"
      "tcgen05.mma.cta_group::1.kind::tf32 [%0], %1, %2, %3, {%5,%5,%5,%5}, p;\n\t}"
      :: "r"(d), "l"(ad), "l"(bd), "r"(IDESC_TF32), "r"(en), "r"(0u) : "memory");
}
__device__ __forceinline__ void tmem_alloc(uint32_t smem_dst, uint32_t ncols){
    asm volatile("tcgen05.alloc.cta_group::1.sync.aligned.shared::cta.b32 [%0], %1;"
                 :: "r"(smem_dst), "r"(ncols) : "memory");
}
__device__ __forceinline__ void tmem_dealloc(uint32_t tmem, uint32_t ncols){
    asm volatile("tcgen05.dealloc.cta_group::1.sync.aligned.b32 %0, %1;" :: "r"(tmem), "r"(ncols));
}
__device__ __forceinline__ void mma_commit(uint32_t mbar){
    asm volatile("tcgen05.commit.cta_group::1.mbarrier::arrive::one.shared::cluster.b64 [%0];"
                 :: "r"(mbar) : "memory");
}
__device__ __forceinline__ void mbar_init(uint32_t mbar, uint32_t cnt){
    asm volatile("mbarrier.init.shared.b64 [%0], %1;" :: "r"(mbar), "r"(cnt) : "memory");
}
__device__ __forceinline__ void mbar_wait(uint32_t mbar, uint32_t parity){
    asm volatile(
      "{\n\t.reg .pred P;\n\t"
      "W0_%=:\n\t"
      "mbarrier.try_wait.parity.acquire.cta.shared::cta.b64 P, [%0], %1, 0x989680;\n\t"
      "@P bra W1_%=;\n\t"
      "bra W0_%=;\n\t"
      "W1_%=:\n\t}"
      :: "r"(mbar), "r"(parity) : "memory");
}
__device__ __forceinline__ void fence_async_shared(){
    asm volatile("fence.proxy.async.shared::cta;" ::: "memory");
}
__device__ __forceinline__ void tc_fence_after(){
    asm volatile("tcgen05.fence::after_thread_sync;" ::: "memory");
}
__device__ __forceinline__ void tc_fence_before(){
    asm volatile("tcgen05.fence::before_thread_sync;" ::: "memory");
}
__device__ __forceinline__ void ldtm32(uint32_t* r, uint32_t tmem_addr){
    asm volatile(
        "tcgen05.ld.sync.aligned.32x32b.x32.b32 "
        "{%0, %1, %2, %3, %4, %5, %6, %7, %8, %9, %10, %11, %12, %13, %14, %15, "
        " %16, %17, %18, %19, %20, %21, %22, %23, %24, %25, %26, %27, %28, %29, %30, %31}, [%32];"
        : "=r"(r[0]),"=r"(r[1]),"=r"(r[2]),"=r"(r[3]),"=r"(r[4]),"=r"(r[5]),"=r"(r[6]),"=r"(r[7]),
          "=r"(r[8]),"=r"(r[9]),"=r"(r[10]),"=r"(r[11]),"=r"(r[12]),"=r"(r[13]),"=r"(r[14]),"=r"(r[15]),
          "=r"(r[16]),"=r"(r[17]),"=r"(r[18]),"=r"(r[19]),"=r"(r[20]),"=r"(r[21]),"=r"(r[22]),"=r"(r[23]),
          "=r"(r[24]),"=r"(r[25]),"=r"(r[26]),"=r"(r[27]),"=r"(r[28]),"=r"(r[29]),"=r"(r[30]),"=r"(r[31])
        : "r"(tmem_addr));
}
__device__ __forceinline__ void tmem_wait_ld(){
    asm volatile("tcgen05.wait::ld.sync.aligned;" ::: "memory");
}
#else
#define HAS_TC 0
#endif

// ---------------- kernel 0: zero output + counts ----------------
__global__ void k_zero(float4* __restrict__ out4){
    int i = blockIdx.x*blockDim.x + threadIdx.x;
    out4[i] = make_float4(0.f,0.f,0.f,0.f);
    if (i < NEXP) g_cnt[i] = 0;
}

// ---------------- kernel 1: router ----------------
__global__ void k_router(const float* __restrict__ x, const float* __restrict__ gw,
                         float* __restrict__ logits_out){
    int warp = (blockIdx.x*blockDim.x + threadIdx.x) >> 5;
    int lane = threadIdx.x & 31;
    if (warp >= TTOK) return;
    const float* xr = x + (size_t)warp*HDIM;
    float acc[NEXP];
    #pragma unroll
    for (int e=0;e<NEXP;e++) acc[e]=0.f;
    for (int i=lane;i<HDIM;i+=32){
        float xv = xr[i];
        #pragma unroll
        for (int e=0;e<NEXP;e++) acc[e] += xv * __ldg(&gw[e*HDIM+i]);
    }
    #pragma unroll
    for (int e=0;e<NEXP;e++){
        float v = acc[e];
        #pragma unroll
        for (int o=16;o>0;o>>=1) v += __shfl_xor_sync(0xffffffffu, v, o);
        acc[e]=v;
    }
    if (lane==0){
        float m = acc[0];
        #pragma unroll
        for (int e=1;e<NEXP;e++) m = fmaxf(m, acc[e]);
        float p[NEXP];
        #pragma unroll
        for (int e=0;e<NEXP;e++){ p[e] = expf(acc[e]-m); logits_out[(size_t)warp*NEXP+e] = acc[e]; }
        int i1 = 0;
        #pragma unroll
        for (int e=1;e<NEXP;e++) if (p[e] > p[i1]) i1 = e;
        int i2 = (i1==0)?1:0;
        #pragma unroll
        for (int e=0;e<NEXP;e++) if (e!=i1 && p[e] > p[i2]) i2 = e;
        float w1=p[i1], w2=p[i2], inv = 1.f/(w1+w2);
        g_tidx[warp*2+0]=i1; g_tw[warp*2+0]=w1*inv;
        g_tidx[warp*2+1]=i2; g_tw[warp*2+1]=w2*inv;
        atomicAdd(&g_cnt[i1],1);
        atomicAdd(&g_cnt[i2],1);
    }
}

// ---------------- kernel 2: scan ----------------
__global__ void k_scan(){
    if (threadIdx.x==0){
        int o=0;
        for (int e=0;e<NEXP;e++){ g_off[e]=o; g_cur[e]=o; o += g_cnt[e]; }
    }
}

// ---------------- kernel 3: placement ----------------
__global__ void k_place(){
    int t = blockIdx.x*blockDim.x + threadIdx.x;
    if (t >= TTOK) return;
    #pragma unroll
    for (int k=0;k<2;k++){
        int e = g_tidx[t*2+k];
        int pos = atomicAdd(&g_cur[e],1);
        g_tok[pos] = t;
        g_wt[pos]  = g_tw[t*2+k];
    }
}

// ================= GEMM 1: gate+up, fused SiLU =================
__global__ __launch_bounds__(256,1) __cluster_dims__(1,1,1) void k_gate_up(
        const float* __restrict__ x,
        const float* __restrict__ wg, const float* __restrict__ wu){
    extern __shared__ __align__(1024) char smem[];
    uint32_t sb = smem_u32(smem);

    int e   = blockIdx.z;
    int cnt = g_cnt[e];
    int m0  = blockIdx.x * BMT;
    if (m0 >= cnt) return;
    int base = g_off[e];
    int tid  = threadIdx.x;
    int wid  = tid >> 5, lane = tid & 31;

#if HAS_TC
    // ---- tcgen05: BM=256 (2xM128 sharing B), BN=128, 3-stage pipeline ----
    int n0 = blockIdx.y * BNT;
    if (wid == 0) tmem_alloc(sb + 0, 512);   // Dg0@0 Du0@128 Dg1@256 Du1@384
    if (tid == 0){ mbar_init(sb+16,1); mbar_init(sb+24,1); mbar_init(sb+32,1); }
    int* stok = (int*)(smem + 64);
    {
        int r = m0 + tid;
        stok[tid] = (r < cnt) ? g_tok[base + r] : g_tok[base];
    }
    __syncthreads();
    uint32_t tmem = *(volatile uint32_t*)(smem + 0);

    const float* wgp = wg + (size_t)e*IDIM*HDIM + (size_t)n0*HDIM;
    const float* wup = wu + (size_t)e*IDIM*HDIM + (size_t)n0*HDIM;

    int lrow = tid >> 3, lc = (tid & 7) * 4;

    float4 ra[8], rbg[4], rbu[4];
    #pragma unroll
    for (int j=0;j<8;j++){
        int row = lrow + j*32;
        ra[j] = *(const float4*)(x + (size_t)stok[row]*HDIM + lc);
    }
    #pragma unroll
    for (int j=0;j<4;j++){
        int row = lrow + j*32;
        rbg[j] = *(const float4*)(wgp + (size_t)row*HDIM + lc);
        rbu[j] = *(const float4*)(wup + (size_t)row*HDIM + lc);
    }

    int ph0=0, ph1=0, ph2=0;
    const int NT = HDIM/BK;
    for (int t = 0; t < NT; t++){
        int s = t - (t/3)*3;
        uint32_t mb = sb + 16 + s*8;
        if (t >= 3){
            if (s==0){ mbar_wait(mb, ph0); ph0^=1; }
            else if (s==1){ mbar_wait(mb, ph1); ph1^=1; }
            else { mbar_wait(mb, ph2); ph2^=1; }
        }
        char* As = smem + GU_A_OFF  + s*32768;
        char* Bg = smem + GU_BG_OFF + s*16384;
        char* Bu = smem + GU_BU_OFF + s*16384;
        #pragma unroll
        for (int j=0;j<8;j++){
            int row = lrow + j*32;
            float4 v = ra[j];
            v.x=tf32r(v.x); v.y=tf32r(v.y); v.z=tf32r(v.z); v.w=tf32r(v.w);
            *(float4*)(As + sw128(row*128 + lc*4)) = v;
        }
        #pragma unroll
        for (int j=0;j<4;j++){
            int row = lrow + j*32;
            float4 v = rbg[j];
            v.x=tf32r(v.x); v.y=tf32r(v.y); v.z=tf32r(v.z); v.w=tf32r(v.w);
            *(float4*)(Bg + sw128(row*128 + lc*4)) = v;
            v = rbu[j];
            v.x=tf32r(v.x); v.y=tf32r(v.y); v.z=tf32r(v.z); v.w=tf32r(v.w);
            *(float4*)(Bu + sw128(row*128 + lc*4)) = v;
        }
        __syncthreads();
        if (tid == 0){
            fence_async_shared();
            uint64_t bgd = make_desc(sb + GU_BG_OFF + s*16384);
            uint64_t bud = make_desc(sb + GU_BU_OFF + s*16384);
            #pragma unroll
            for (int m=0;m<2;m++){
                uint64_t ad = make_desc(sb + GU_A_OFF + s*32768 + m*16384);
                #pragma unroll
                for (int c8=0;c8<4;c8++){
                    mma_tf32(tmem + m*256,       ad + 2*c8, bgd + 2*c8, (uint32_t)(t | c8));
                    mma_tf32(tmem + m*256 + 128, ad + 2*c8, bud + 2*c8, (uint32_t)(t | c8));
                }
            }
            mma_commit(mb);
        }
        if (t + 1 < NT){
            int kk = (t+1) * BK;
            #pragma unroll
            for (int j=0;j<8;j++){
                int row = lrow + j*32;
                ra[j] = *(const float4*)(x + (size_t)stok[row]*HDIM + kk + lc);
            }
            #pragma unroll
            for (int j=0;j<4;j++){
                int row = lrow + j*32;
                rbg[j] = *(const float4*)(wgp + (size_t)row*HDIM + kk + lc);
                rbu[j] = *(const float4*)(wup + (size_t)row*HDIM + kk + lc);
            }
        }
    }
    mbar_wait(sb+16, ph0);
    mbar_wait(sb+24, ph1);
    mbar_wait(sb+32, ph2);
    tc_fence_after();
    {
        int m = wid >> 2;                      // mtile 0/1
        int rloc = m*128 + (wid&3)*32 + lane;  // local row in [0,256)
        int r    = m0 + rloc;
        #pragma unroll
        for (int it=0; it<4; it++){
            int cb = it*32;
            uint32_t gv[32], uv[32];
            ldtm32(gv, tmem + m*256 + cb);
            ldtm32(uv, tmem + m*256 + 128 + cb);
            tmem_wait_ld();
            if (r < cnt){
                float o[32];
                #pragma unroll
                for (int j=0;j<32;j++){
                    float g = __uint_as_float(gv[j]);
                    float u = __uint_as_float(uv[j]);
                    o[j] = g/(1.f+expf(-g))*u;
                }
                float* dst = g_act + (size_t)(base + r)*IDIM + n0 + cb;
                #pragma unroll
                for (int j=0;j<8;j++)
                    *(float4*)(dst + j*4) = make_float4(o[j*4],o[j*4+1],o[j*4+2],o[j*4+3]);
            }
        }
    }
    tc_fence_before();
    __syncthreads();
    if (wid == 0) tmem_dealloc(tmem, 512);
#else
    // ---- legacy mma.sync + ldmatrix fallback (PTX pass only; never runs on a-SASS) ----
    const uint32_t OFF_A = 0, OFF_BG = 18432, OFF_BU = 27648;
    float (*As)[KP] = (float(*)[KP])(smem + OFF_A);
    float (*Bg)[KP] = (float(*)[KP])(smem + OFF_BG);
    float (*Bu)[KP] = (float(*)[KP])(smem + OFF_BU);
    int* stok = (int*)(smem + 36864);

    const float* wgp = wg + (size_t)e*IDIM*HDIM;
    const float* wup = wu + (size_t)e*IDIM*HDIM;

    int wm = (wid&3)*32, wn = (wid>>2)*32;
    int lr = lane & 7, sel = lane >> 3;
    uint32_t aoff[2], bgoff[2], buoff[2];
    #pragma unroll
    for (int mi=0;mi<2;mi++){
        int row = wm + mi*16 + (sel&1)*8 + lr;
        int c0  = (sel>>1)*4;
        aoff[mi] = sb + OFF_A + (uint32_t)(row*KP + c0)*4u;
    }
    #pragma unroll
    for (int nq=0;nq<2;nq++){
        int row = wn + nq*16 + (sel>>1)*8 + lr;
        int c0  = (sel&1)*4;
        bgoff[nq] = sb + OFF_BG + (uint32_t)(row*KP + c0)*4u;
        buoff[nq] = sb + OFF_BU + (uint32_t)(row*KP + c0)*4u;
    }

    for (int mpass=0; mpass<2; mpass++){
        int m0L = m0 + mpass*128;
        if (m0L >= cnt) break;
        __syncthreads();
        if (tid < 128){
            int r = m0L + tid;
            stok[tid] = (r < cnt) ? g_tok[base + r] : g_tok[base];
        }
        __syncthreads();

        for (int hpass = 0; hpass < 2; hpass++){
            int n0 = blockIdx.y * BNT + hpass*64;
            __syncthreads();

            float cg[2][4][4], cu[2][4][4];
            #pragma unroll
            for (int mi=0;mi<2;mi++)
                #pragma unroll
                for (int ni=0;ni<4;ni++)
                    #pragma unroll
                    for (int q=0;q<4;q++){ cg[mi][ni][q]=0.f; cu[mi][ni][q]=0.f; }

            float4 ra[4], rbg[2], rbu[2];
            #pragma unroll
            for (int j=0;j<4;j++){
                int i = tid + j*256; int row = i>>3, k4 = i&7;
                ra[j] = *(const float4*)(&x[(size_t)stok[row]*HDIM + k4*4]);
            }
            #pragma unroll
            for (int j=0;j<2;j++){
                int i = tid + j*256; int n = i>>3, k4 = i&7;
                rbg[j] = *(const float4*)(&wgp[(size_t)(n0+n)*HDIM + k4*4]);
                rbu[j] = *(const float4*)(&wup[(size_t)(n0+n)*HDIM + k4*4]);
            }
            #pragma unroll
            for (int j=0;j<4;j++){
                int i = tid + j*256; int row = i>>3, k4 = i&7;
                As[row][k4*4+0]=tf32r(ra[j].x); As[row][k4*4+1]=tf32r(ra[j].y);
                As[row][k4*4+2]=tf32r(ra[j].z); As[row][k4*4+3]=tf32r(ra[j].w);
            }
            #pragma unroll
            for (int j=0;j<2;j++){
                int i = tid + j*256; int n = i>>3, k4 = i&7;
                Bg[n][k4*4+0]=tf32r(rbg[j].x); Bg[n][k4*4+1]=tf32r(rbg[j].y);
                Bg[n][k4*4+2]=tf32r(rbg[j].z); Bg[n][k4*4+3]=tf32r(rbg[j].w);
                Bu[n][k4*4+0]=tf32r(rbu[j].x); Bu[n][k4*4+1]=tf32r(rbu[j].y);
                Bu[n][k4*4+2]=tf32r(rbu[j].z); Bu[n][k4*4+3]=tf32r(rbu[j].w);
            }
            __syncthreads();

            for (int kk = BK; kk <= HDIM; kk += BK){
                bool more = (kk < HDIM);
                if (more){
                    #pragma unroll
                    for (int j=0;j<4;j++){
                        int i = tid + j*256; int row = i>>3, k4 = i&7;
                        ra[j] = *(const float4*)(&x[(size_t)stok[row]*HDIM + kk + k4*4]);
                    }
                    #pragma unroll
                    for (int j=0;j<2;j++){
                        int i = tid + j*256; int n = i>>3, k4 = i&7;
                        rbg[j] = *(const float4*)(&wgp[(size_t)(n0+n)*HDIM + kk + k4*4]);
                        rbu[j] = *(const float4*)(&wup[(size_t)(n0+n)*HDIM + kk + k4*4]);
                    }
                }
                #pragma unroll
                for (int k8=0;k8<BK;k8+=8){
                    uint32_t kb = (uint32_t)k8*4u;
                    uint32_t a[2][4], bgf[2][4], buf[2][4];
                    ldsm4(a[0],  aoff[0]  + kb);
                    ldsm4(a[1],  aoff[1]  + kb);
                    ldsm4(bgf[0], bgoff[0] + kb);
                    ldsm4(bgf[1], bgoff[1] + kb);
                    ldsm4(buf[0], buoff[0] + kb);
                    ldsm4(buf[1], buoff[1] + kb);
                    #pragma unroll
                    for (int ni=0;ni<4;ni++){
                        int q = ni>>1, ix = (ni&1)*2;
                        #pragma unroll
                        for (int mi=0;mi<2;mi++){
                            mma8(cg[mi][ni], a[mi], bgf[q][ix], bgf[q][ix+1]);
                            mma8(cu[mi][ni], a[mi], buf[q][ix], buf[q][ix+1]);
                        }
                    }
                }
                __syncthreads();
                if (more){
                    #pragma unroll
                    for (int j=0;j<4;j++){
                        int i = tid + j*256; int row = i>>3, k4 = i&7;
                        As[row][k4*4+0]=tf32r(ra[j].x); As[row][k4*4+1]=tf32r(ra[j].y);
                        As[row][k4*4+2]=tf32r(ra[j].z); As[row][k4*4+3]=tf32r(ra[j].w);
                    }
                    #pragma unroll
                    for (int j=0;j<2;j++){
                        int i = tid + j*256; int n = i>>3, k4 = i&7;
                        Bg[n][k4*4+0]=tf32r(rbg[j].x); Bg[n][k4*4+1]=tf32r(rbg[j].y);
                        Bg[n][k4*4+2]=tf32r(rbg[j].z); Bg[n][k4*4+3]=tf32r(rbg[j].w);
                        Bu[n][k4*4+0]=tf32r(rbu[j].x); Bu[n][k4*4+1]=tf32r(rbu[j].y);
                        Bu[n][k4*4+2]=tf32r(rbu[j].z); Bu[n][k4*4+3]=tf32r(rbu[j].w);
                    }
                    __syncthreads();
                }
            }

            int grp = lane>>2, thr = lane&3;
            #pragma unroll
            for (int mi=0;mi<2;mi++){
                #pragma unroll
                for (int ni=0;ni<4;ni++){
                    int ncol = n0 + wn + ni*8 + 2*thr;
                    #pragma unroll
                    for (int h=0;h<2;h++){
                        int r = m0L + wm + mi*16 + grp + h*8;
                        if (r < cnt){
                            size_t ro = (size_t)(base + r)*IDIM;
                            float g0 = cg[mi][ni][h*2+0], g1 = cg[mi][ni][h*2+1];
                            float u0 = cu[mi][ni][h*2+0], u1 = cu[mi][ni][h*2+1];
                            g_act[ro + ncol  ] = g0/(1.f+expf(-g0))*u0;
                            g_act[ro + ncol+1] = g1/(1.f+expf(-g1))*u1;
                        }
                    }
                }
            }
        }
    }
#endif
}

// ================= GEMM 2: down + weighted scatter =================
__global__ __launch_bounds__(256,1) __cluster_dims__(1,1,1) void k_down(
        const float* __restrict__ wd, float* __restrict__ out){
    extern __shared__ __align__(1024) char smem[];
    uint32_t sb = smem_u32(smem);

    int e   = blockIdx.z;
    int cnt = g_cnt[e];
    int m0  = blockIdx.x * BMT;
    if (m0 >= cnt) return;
    int base = g_off[e];
    int tid  = threadIdx.x;
    int wid  = tid >> 5, lane = tid & 31;

#if HAS_TC
    int n0 = blockIdx.y * BNT;
    if (wid == 0) tmem_alloc(sb + 0, 256);   // D0@0, D1@128
    if (tid == 0){ mbar_init(sb+16,1); mbar_init(sb+24,1); mbar_init(sb+32,1); }
    int*   stok = (int*)(smem + 64);
    float* swt  = (float*)(smem + 1088);
    {
        int r = m0 + tid;
        bool v = (r < cnt);
        stok[tid] = v ? g_tok[base + r] : 0;
        swt[tid]  = v ? g_wt[base + r] : 0.f;
    }
    __syncthreads();
    uint32_t tmem = *(volatile uint32_t*)(smem + 0);

    const float* wdp = wd + (size_t)e*HDIM*IDIM + (size_t)n0*IDIM;
    const float* ap  = g_act + (size_t)(base + m0)*IDIM;
    int rmax = cnt - m0;

    int lrow = tid >> 3, lc = (tid & 7) * 4;

    float4 ra[8], rb[4];
    #pragma unroll
    for (int j=0;j<8;j++){
        int row = lrow + j*32;
        int rr  = (row < rmax) ? row : 0;
        ra[j] = *(const float4*)(ap + (size_t)rr*IDIM + lc);
    }
    #pragma unroll
    for (int j=0;j<4;j++){
        int row = lrow + j*32;
        rb[j] = *(const float4*)(wdp + (size_t)row*IDIM + lc);
    }

    int ph0=0, ph1=0, ph2=0;
    const int NT = IDIM/BK;
    for (int t = 0; t < NT; t++){
        int s = t - (t/3)*3;
        uint32_t mb = sb + 16 + s*8;
        if (t >= 3){
            if (s==0){ mbar_wait(mb, ph0); ph0^=1; }
            else if (s==1){ mbar_wait(mb, ph1); ph1^=1; }
            else { mbar_wait(mb, ph2); ph2^=1; }
        }
        char* As = smem + DN_A_OFF + s*32768;
        char* Bs = smem + DN_B_OFF + s*16384;
        #pragma unroll
        for (int j=0;j<8;j++){
            int row = lrow + j*32;
            float4 v = ra[j];
            v.x=tf32r(v.x); v.y=tf32r(v.y); v.z=tf32r(v.z); v.w=tf32r(v.w);
            *(float4*)(As + sw128(row*128 + lc*4)) = v;
        }
        #pragma unroll
        for (int j=0;j<4;j++){
            int row = lrow + j*32;
            float4 v = rb[j];
            v.x=tf32r(v.x); v.y=tf32r(v.y); v.z=tf32r(v.z); v.w=tf32r(v.w);
            *(float4*)(Bs + sw128(row*128 + lc*4)) = v;
        }
        __syncthreads();
        if (tid == 0){
            fence_async_shared();
            uint64_t bd = make_desc(sb + DN_B_OFF + s*16384);
            #pragma unroll
            for (int m=0;m<2;m++){
                uint64_t ad = make_desc(sb + DN_A_OFF + s*32768 + m*16384);
                #pragma unroll
                for (int c8=0;c8<4;c8++)
                    mma_tf32(tmem + m*128, ad + 2*c8, bd + 2*c8, (uint32_t)(t | c8));
            }
            mma_commit(mb);
        }
        if (t + 1 < NT){
            int kk = (t+1) * BK;
            #pragma unroll
            for (int j=0;j<8;j++){
                int row = lrow + j*32;
                int rr  = (row < rmax) ? row : 0;
                ra[j] = *(const float4*)(ap + (size_t)rr*IDIM + kk + lc);
            }
            #pragma unroll
            for (int j=0;j<4;j++){
                int row = lrow + j*32;
                rb[j] = *(const float4*)(wdp + (size_t)row*IDIM + kk + lc);
            }
        }
    }
    mbar_wait(sb+16, ph0);
    mbar_wait(sb+24, ph1);
    mbar_wait(sb+32, ph2);
    tc_fence_after();
    {
        int m = wid >> 2;
        int rloc = m*128 + (wid&3)*32 + lane;
        int r    = m0 + rloc;
        float w  = swt[rloc];
        int tok  = stok[rloc];
        #pragma unroll
        for (int it=0; it<4; it++){
            int cb = it*32;
            uint32_t dv[32];
            ldtm32(dv, tmem + m*128 + cb);
            tmem_wait_ld();
            if (r < cnt){
                float* dst = out + (size_t)tok*HDIM + n0 + cb;
                #pragma unroll
                for (int j=0;j<32;j++)
                    atomicAdd(dst + j, __uint_as_float(dv[j]) * w);
            }
        }
    }
    tc_fence_before();
    __syncthreads();
    if (wid == 0) tmem_dealloc(tmem, 256);
#else
    const uint32_t OFF_A = 0, OFF_B = 18432;
    float (*As)[KP] = (float(*)[KP])(smem + OFF_A);
    float (*Bs)[KP] = (float(*)[KP])(smem + OFF_B);
    int*   stok = (int*)(smem + 27648);
    float* swt  = (float*)(smem + 28160);

    const float* wdp = wd + (size_t)e*HDIM*IDIM;

    int wm = (wid&3)*32, wn = (wid>>2)*32;
    int lr = lane & 7, sel = lane >> 3;
    uint32_t aoff[2], boff[2];
    #pragma unroll
    for (int mi=0;mi<2;mi++){
        int row = wm + mi*16 + (sel&1)*8 + lr;
        int c0  = (sel>>1)*4;
        aoff[mi] = sb + OFF_A + (uint32_t)(row*KP + c0)*4u;
    }
    #pragma unroll
    for (int nq=0;nq<2;nq++){
        int row = wn + nq*16 + (sel>>1)*8 + lr;
        int c0  = (sel&1)*4;
        boff[nq] = sb + OFF_B + (uint32_t)(row*KP + c0)*4u;
    }

    for (int mpass=0; mpass<2; mpass++){
        int m0L = m0 + mpass*128;
        if (m0L >= cnt) break;
        __syncthreads();
        if (tid < 128){
            int r = m0L + tid;
            bool v = (r < cnt);
            stok[tid] = v ? g_tok[base + r] : 0;
            swt[tid]  = v ? g_wt[base + r] : 0.f;
        }
        __syncthreads();

        for (int hpass = 0; hpass < 2; hpass++){
            int n0 = blockIdx.y * BNT + hpass*64;
            __syncthreads();

            float cc[2][4][4];
            #pragma unroll
            for (int mi=0;mi<2;mi++)
                #pragma unroll
                for (int ni=0;ni<4;ni++)
                    #pragma unroll
                    for (int q=0;q<4;q++) cc[mi][ni][q]=0.f;

            float4 ra[4], rb[2];
            #pragma unroll
            for (int j=0;j<4;j++){
                int i = tid + j*256; int row = i>>3, k4 = i&7;
                int rr = m0L + row; if (rr >= cnt) rr = m0L;
                ra[j] = *(const float4*)(&g_act[(size_t)(base+rr)*IDIM + k4*4]);
            }
            #pragma unroll
            for (int j=0;j<2;j++){
                int i = tid + j*256; int n = i>>3, k4 = i&7;
                rb[j] = *(const float4*)(&wdp[(size_t)(n0+n)*IDIM + k4*4]);
            }
            #pragma unroll
            for (int j=0;j<4;j++){
                int i = tid + j*256; int row = i>>3, k4 = i&7;
                As[row][k4*4+0]=tf32r(ra[j].x); As[row][k4*4+1]=tf32r(ra[j].y);
                As[row][k4*4+2]=tf32r(ra[j].z); As[row][k4*4+3]=tf32r(ra[j].w);
            }
            #pragma unroll
            for (int j=0;j<2;j++){
                int i = tid + j*256; int n = i>>3, k4 = i&7;
                Bs[n][k4*4+0]=tf32r(rb[j].x); Bs[n][k4*4+1]=tf32r(rb[j].y);
                Bs[n][k4*4+2]=tf32r(rb[j].z); Bs[n][k4*4+3]=tf32r(rb[j].w);
            }
            __syncthreads();

            for (int kk = BK; kk <= IDIM; kk += BK){
                bool more = (kk < IDIM);
                if (more){
                    #pragma unroll
                    for (int j=0;j<4;j++){
                        int i = tid + j*256; int row = i>>3, k4 = i&7;
                        int rr = m0L + row; if (rr >= cnt) rr = m0L;
                        ra[j] = *(const float4*)(&g_act[(size_t)(base+rr)*IDIM + kk + k4*4]);
                    }
                    #pragma unroll
                    for (int j=0;j<2;j++){
                        int i = tid + j*256; int n = i>>3, k4 = i&7;
                        rb[j] = *(const float4*)(&wdp[(size_t)(n0+n)*IDIM + kk + k4*4]);
                    }
                }
                #pragma unroll
                for (int k8=0;k8<BK;k8+=8){
                    uint32_t kb = (uint32_t)k8*4u;
                    uint32_t a[2][4], bf[2][4];
                    ldsm4(a[0], aoff[0] + kb);
                    ldsm4(a[1], aoff[1] + kb);
                    ldsm4(bf[0], boff[0] + kb);
                    ldsm4(bf[1], boff[1] + kb);
                    #pragma unroll
                    for (int ni=0;ni<4;ni++){
                        int q = ni>>1, ix = (ni&1)*2;
                        #pragma unroll
                        for (int mi=0;mi<2;mi++)
                            mma8(cc[mi][ni], a[mi], bf[q][ix], bf[q][ix+1]);
                    }
                }
                __syncthreads();
                if (more){
                    #pragma unroll
                    for (int j=0;j<4;j++){
                        int i = tid + j*256; int row = i>>3, k4 = i&7;
                        int rr = m0L + row; if (rr >= cnt) rr = m0L;
                        ra[j] = *(const float4*)(&g_act[(size_t)(base+rr)*IDIM + kk + k4*4]);
                    }
                    #pragma unroll
                    for (int j=0;j<4;j++){
                        int i = tid + j*256; int row = i>>3, k4 = i&7;
                        As[row][k4*4+0]=tf32r(ra[j].x); As[row][k4*4+1]=tf32r(ra[j].y);
                        As[row][k4*4+2]=tf32r(ra[j].z); As[row][k4*4+3]=tf32r(ra[j].w);
                    }
                    #pragma unroll
                    for (int j=0;j<2;j++){
                        int i = tid + j*256; int n = i>>3, k4 = i&7;
                        Bs[n][k4*4+0]=tf32r(rb[j].x); Bs[n][k4*4+1]=tf32r(rb[j].y);
                        Bs[n][k4*4+2]=tf32r(rb[j].z); Bs[n][k4*4+3]=tf32r(rb[j].w);
                    }
                    __syncthreads();
                }
            }

            int grp = lane>>2, thr = lane&3;
            #pragma unroll
            for (int mi=0;mi<2;mi++){
                #pragma unroll
                for (int ni=0;ni<4;ni++){
                    int ncol = n0 + wn + ni*8 + 2*thr;
                    #pragma unroll
                    for (int h=0;h<2;h++){
                        int rloc = wm + mi*16 + grp + h*8;
                        int r = m0L + rloc;
                        if (r < cnt){
                            float w = swt[rloc];
                            size_t o = (size_t)stok[rloc]*HDIM + ncol;
                            atomicAdd(&out[o  ], cc[mi][ni][h*2+0]*w);
                            atomicAdd(&out[o+1], cc[mi][ni][h*2+1]*w);
                        }
                    }
                }
            }
        }
    }
#endif
}

// ---------------- launch ----------------
extern "C" void kernel_launch(void* const* d_in, const int* in_sizes, int n_in,
                              void* d_out, int out_size){
    const float* x  = (const float*)d_in[0];
    const float* gw = (const float*)d_in[1];
    const float* wg = (const float*)d_in[2];
    const float* wu = (const float*)d_in[3];
    const float* wd = (const float*)d_in[4];
    float* out = (float*)d_out;

    cudaFuncSetAttribute(k_gate_up, cudaFuncAttributeMaxDynamicSharedMemorySize, GU_SMEM);
    cudaFuncSetAttribute(k_down,    cudaFuncAttributeMaxDynamicSharedMemorySize, DN_SMEM);

    k_zero<<<FINAL_ELEMS/4/256, 256>>>((float4*)out);
    k_router<<<TTOK/4, 128>>>(x, gw, out + FINAL_ELEMS);
    k_scan<<<1, 32>>>();
    k_place<<<TTOK/256, 256>>>();
    dim3 g1(TTOK/BMT, IDIM/BNT, NEXP);   // (16, 11, 8)
    k_gate_up<<<g1, 256, GU_SMEM>>>(x, wg, wu);
    dim3 g2(TTOK/BMT, HDIM/BNT, NEXP);   // (16, 16, 8)
    k_down<<<g2, 256, DN_SMEM>>>(wd, out);
}